// round 11
// baseline (speedup 1.0000x reference)
#include <cuda_runtime.h>
#include <cuda_fp16.h>
#include <math.h>
#include <stdint.h>

#define Bc     8
#define Nc     1000
#define Dc     64
#define ADc    32
#define NEc    4000      // E * N
#define ACOLS  8000      // 2 * E * N
#define KCH    32        // K per chunk
#define NCHUNK 125       // 4000 / 32
#define ASTR   40        // fp16 A smem stride (halves)
#define ASTR32 36        // fp32 A smem stride (floats)
#define BSTR   72        // B smem stride (halves)

// Scratch (static device globals; no allocation)
__device__ __half g_Ah[(size_t)Bc * Nc * ACOLS];   // fp16 copy of A (128 MB)
__device__ __half g_sh[2][Bc][NEc][Dc];            // S (fp16), k-major rows
__device__ float  g_a[2][Bc][Nc][Dc];              // a_in / a_out
__device__ float  g_state[2][Bc][Nc][Dc];          // s1 / s2
__device__ float  g_P[Bc * Nc][192];               // GRU pre-activations
__device__ float  g_WT[192][192];                  // [k][out]: r|z|h (h state-cols zeroed)
__device__ float  g_Wh2T[Dc][Dc];                  // [k][f] = W_h[f][128+k]

// ---------------------------------------------------------------------------
// helpers
// ---------------------------------------------------------------------------
__device__ __forceinline__ void cp_async16(uint32_t dst, const void* src) {
    asm volatile("cp.async.cg.shared.global [%0], [%1], 16;\n" :: "r"(dst), "l"(src));
}
__device__ __forceinline__ void cp_commit() {
    asm volatile("cp.async.commit_group;\n");
}
__device__ __forceinline__ void ldm4(uint32_t* r, uint32_t addr) {
    asm volatile("ldmatrix.sync.aligned.m8n8.x4.shared.b16 {%0,%1,%2,%3}, [%4];"
                 : "=r"(r[0]), "=r"(r[1]), "=r"(r[2]), "=r"(r[3]) : "r"(addr));
}
__device__ __forceinline__ void ldm4t(uint32_t* r, uint32_t addr) {
    asm volatile("ldmatrix.sync.aligned.m8n8.x4.trans.shared.b16 {%0,%1,%2,%3}, [%4];"
                 : "=r"(r[0]), "=r"(r[1]), "=r"(r[2]), "=r"(r[3]) : "r"(addr));
}
__device__ __forceinline__ void mma_f16(float* c, const uint32_t* a,
                                        uint32_t b0, uint32_t b1) {
    asm volatile("mma.sync.aligned.m16n8k16.row.col.f32.f16.f16.f32 "
                 "{%0,%1,%2,%3},{%4,%5,%6,%7},{%8,%9},{%0,%1,%2,%3};"
                 : "+f"(c[0]), "+f"(c[1]), "+f"(c[2]), "+f"(c[3])
                 : "r"(a[0]), "r"(a[1]), "r"(a[2]), "r"(a[3]), "r"(b0), "r"(b1));
}

// ---------------------------------------------------------------------------
// One-time weight transposes for the GRU GEMMs
// ---------------------------------------------------------------------------
__global__ void __launch_bounds__(256) k_prepW(const float* __restrict__ W_r,
                                               const float* __restrict__ W_z,
                                               const float* __restrict__ W_h) {
    int idx = blockIdx.x * 256 + threadIdx.x;
    if (idx < 192 * 192) {
        int k = idx / 192, out = idx % 192;
        int grp = out >> 6, f = out & 63;
        const float* W = (grp == 0) ? W_r : (grp == 1) ? W_z : W_h;
        float v = W[f * 192 + k];
        if (grp == 2 && k >= 128) v = 0.f;
        g_WT[k][out] = v;
    }
    if (idx < 64 * 64) {
        int k = idx / 64, f = idx % 64;
        g_Wh2T[k][f] = W_h[f * 192 + 128 + k];
    }
}

// ---------------------------------------------------------------------------
// s projection (tiled GEMM) -> fp16 S, k-major rows
// grid (125, 8), block 256.
// ---------------------------------------------------------------------------
__global__ void __launch_bounds__(256) k_compute_s2(
    const float* __restrict__ Xext, int use_ext,
    const float* __restrict__ W_in, const float* __restrict__ W_out) {
    const float* X = use_ext ? Xext : &g_state[0][0][0][0];
    int rb = blockIdx.x, cb = blockIdx.y;
    __shared__ float x_sm[64][64];
    __shared__ float wT[64][64];
    int t = threadIdx.x;

#pragma unroll
    for (int i = 0; i < 4; i++) {
        int idx = i * 256 + t;
        int r = idx >> 4, c4 = idx & 15;
        int gr = rb * 64 + r;
        *(float4*)&x_sm[r][c4 * 4] = *(const float4*)&X[(size_t)gr * 64 + c4 * 4];
    }
    const float* Wsrc = (cb < 4) ? (W_in + (size_t)cb * 64 * 64)
                                 : (W_out + (size_t)(cb - 4) * 64 * 64);
#pragma unroll
    for (int i = 0; i < 4; i++) {
        int idx = i * 256 + t;
        int cl = idx >> 4, k4 = idx & 15;
        float4 v = *(const float4*)&Wsrc[cl * 64 + k4 * 4];
        wT[k4 * 4 + 0][cl] = v.x;
        wT[k4 * 4 + 1][cl] = v.y;
        wT[k4 * 4 + 2][cl] = v.z;
        wT[k4 * 4 + 3][cl] = v.w;
    }
    __syncthreads();

    int ty = t >> 5, tx = t & 31;
    float acc[8][2];
#pragma unroll
    for (int i = 0; i < 8; i++) { acc[i][0] = 0.f; acc[i][1] = 0.f; }

#pragma unroll
    for (int k4 = 0; k4 < 16; k4++) {
        float4 xv[8];
#pragma unroll
        for (int i = 0; i < 8; i++) xv[i] = *(float4*)&x_sm[ty * 8 + i][k4 * 4];
#pragma unroll
        for (int q = 0; q < 4; q++) {
            float2 wv = *(float2*)&wT[k4 * 4 + q][tx * 2];
#pragma unroll
            for (int i = 0; i < 8; i++) {
                float xs = (q == 0) ? xv[i].x : (q == 1) ? xv[i].y
                         : (q == 2) ? xv[i].z : xv[i].w;
                acc[i][0] += xs * wv.x;
                acc[i][1] += xs * wv.y;
            }
        }
    }

    int cbase = cb * 64 + tx * 2;
    int half = cbase >> 8, e = (cbase >> 6) & 3, f = cbase & 63;
#pragma unroll
    for (int i = 0; i < 8; i++) {
        int gr = rb * 64 + ty * 8 + i;
        int b = gr / 1000, n = gr % 1000;
        __half2 hv = __floats2half2_rn(acc[i][0], acc[i][1]);
        *(__half2*)&g_sh[half][b][e * 1000 + n][f] = hv;
    }
}

// ---------------------------------------------------------------------------
// Big adjacency GEMM, PASS 1 (fused A fp32->fp16 conversion):
// reads A fp32 via cp.async, converts to fp16 in smem (+ writes g_Ah for
// pass 2), then identical ldmatrix/mma body. grid (16, 2, 8), 128 threads.
// Dynamic smem: [4][64*36] fp32 A stages | [64*40] fp16 A buf | [4][32*72] B.
// ---------------------------------------------------------------------------
#define A32_STAGE (64 * ASTR32)                    // floats per stage
#define OFF_AH16  (4 * A32_STAGE * 4)              // 36864 B
#define OFF_BSM   (OFF_AH16 + 64 * ASTR * 2)       // 41984 B
#define DSM_CVT   (OFF_BSM + 4 * 32 * BSTR * 2)    // 60416 B

__global__ void __launch_bounds__(128) k_biggemm_f32cvt(const float* __restrict__ A) {
    extern __shared__ char dsm[];
    float*  As32 = (float*)dsm;                    // [4][64*36]
    __half* Ah16 = (__half*)(dsm + OFF_AH16);      // [64*40]
    __half* Bsm  = (__half*)(dsm + OFF_BSM);       // [4][32*72]

    int rb = blockIdx.x, half = blockIdx.y, b = blockIdx.z;
    int row0 = rb * 64;
    const float*  Abf = A + (size_t)b * Nc * ACOLS + (size_t)half * NEc;
    __half*       ghA = g_Ah + (size_t)b * Nc * ACOLS + (size_t)half * NEc;
    const __half* Sbh = &g_sh[half][b][0][0];

    int t = threadIdx.x, lane = t & 31, warp = t >> 5;

    // A cp.async mapping: 64 rows x 8 segs of 16B (4 floats)
    const float* asrc[4]; uint32_t adst[4]; __half* ahdst[4]; int arow[4], aseg[4];
#pragma unroll
    for (int j = 0; j < 4; j++) {
        int flat = j * 128 + t;
        int row = flat >> 3, seg = flat & 7;
        int gr = row0 + row; if (gr > Nc - 1) gr = Nc - 1;
        asrc[j] = Abf + (size_t)gr * ACOLS + seg * 4;
        adst[j] = (uint32_t)(row * ASTR32 + seg * 4) * 4u;
        ahdst[j] = ghA + (size_t)gr * ACOLS + seg * 4;
        arow[j] = row; aseg[j] = seg;
    }
    // B cp.async mapping: 32 rows x 8 segs of 16B (8 halves)
    const __half* bsrc[2]; uint32_t bdst[2];
#pragma unroll
    for (int j = 0; j < 2; j++) {
        int flat = j * 128 + t;
        int row = flat >> 3, seg = flat & 7;
        bsrc[j] = Sbh + (size_t)row * Dc + seg * 8;
        bdst[j] = (uint32_t)(row * BSTR + seg * 8) * 2u;
    }

    uint32_t a32_base[4], b_base[4];
#pragma unroll
    for (int s = 0; s < 4; s++) {
        a32_base[s] = (uint32_t)__cvta_generic_to_shared(As32 + s * A32_STAGE);
        b_base[s]   = (uint32_t)__cvta_generic_to_shared(Bsm + s * 32 * BSTR);
    }
    uint32_t ah_base = (uint32_t)__cvta_generic_to_shared(Ah16);

    // ldmatrix offsets (fp16 A buf, stride ASTR; B stages, stride BSTR)
    uint32_t a_off[2];
#pragma unroll
    for (int kk = 0; kk < 2; kk++) {
        int row = warp * 16 + ((lane >> 3) & 1) * 8 + (lane & 7);
        int col = kk * 16 + (lane >> 4) * 8;
        a_off[kk] = ah_base + (uint32_t)(row * ASTR + col) * 2u;
    }
    uint32_t b_off[4][2];
#pragma unroll
    for (int g = 0; g < 4; g++)
#pragma unroll
        for (int kk = 0; kk < 2; kk++) {
            int krow = kk * 16 + (lane & 15);
            int ncol = g * 16 + (lane >> 4) * 8;
            b_off[g][kk] = (uint32_t)(krow * BSTR + ncol) * 2u;
        }

    float acc[8][4];
#pragma unroll
    for (int nt = 0; nt < 8; nt++)
#pragma unroll
        for (int c = 0; c < 4; c++) acc[nt][c] = 0.f;

    // prologue: chunks 0..2
#pragma unroll
    for (int ch = 0; ch < 3; ch++) {
        int kt = ch * KCH;
#pragma unroll
        for (int j = 0; j < 4; j++) cp_async16(a32_base[ch] + adst[j], asrc[j] + kt);
#pragma unroll
        for (int j = 0; j < 2; j++) cp_async16(b_base[ch] + bdst[j], bsrc[j] + (size_t)kt * Dc);
        cp_commit();
    }

    for (int i = 0; i < NCHUNK; i++) {
        asm volatile("cp.async.wait_group 2;\n");
        __syncthreads();

        if (i + 3 < NCHUNK) {
            int s = (i + 3) & 3;
            int kt = (i + 3) * KCH;
#pragma unroll
            for (int j = 0; j < 4; j++) cp_async16(a32_base[s] + adst[j], asrc[j] + kt);
#pragma unroll
            for (int j = 0; j < 2; j++) cp_async16(b_base[s] + bdst[j], bsrc[j] + (size_t)kt * Dc);
        }
        cp_commit();

        // convert this stage's A fp32 -> fp16 buffer (+ global fp16 copy)
        {
            const float* src = As32 + (i & 3) * A32_STAGE;
            int kt = i * KCH;
#pragma unroll
            for (int j = 0; j < 4; j++) {
                float4 v = *(const float4*)&src[arow[j] * ASTR32 + aseg[j] * 4];
                __half2 h0 = __floats2half2_rn(v.x, v.y);
                __half2 h1 = __floats2half2_rn(v.z, v.w);
                uint2 pk = make_uint2(*(uint32_t*)&h0, *(uint32_t*)&h1);
                *(uint2*)&Ah16[arow[j] * ASTR + aseg[j] * 4] = pk;
                *(uint2*)(ahdst[j] + kt) = pk;
            }
        }
        __syncthreads();

        uint32_t bb = b_base[i & 3];
        uint32_t aF[2][4];
        uint32_t bF[2][4][4];
#pragma unroll
        for (int kk = 0; kk < 2; kk++) ldm4(aF[kk], a_off[kk]);
#pragma unroll
        for (int kk = 0; kk < 2; kk++)
#pragma unroll
            for (int g = 0; g < 4; g++) ldm4t(bF[kk][g], bb + b_off[g][kk]);

#pragma unroll
        for (int kk = 0; kk < 2; kk++)
#pragma unroll
            for (int nt = 0; nt < 8; nt++) {
                int g = nt >> 1, sel = nt & 1;
                mma_f16(acc[nt], aF[kk],
                        bF[kk][g][sel * 2], bF[kk][g][sel * 2 + 1]);
            }
    }

    float (*C)[Dc] = g_a[half][b];
    int r_a = row0 + warp * 16 + (lane >> 2);
    int r_b = r_a + 8;
#pragma unroll
    for (int nt = 0; nt < 8; nt++) {
        int col = nt * 8 + (lane & 3) * 2;
        if (r_a < Nc) *(float2*)&C[r_a][col] = make_float2(acc[nt][0], acc[nt][1]);
        if (r_b < Nc) *(float2*)&C[r_b][col] = make_float2(acc[nt][2], acc[nt][3]);
    }
}

// ---------------------------------------------------------------------------
// Big adjacency GEMM, PASS 2 (pure fp16, R8 config):
// grid (16, 2, 8), 128 threads (4 warps; warp tile 16m x 64n). 39 KB smem.
// ---------------------------------------------------------------------------
__global__ void __launch_bounds__(128) k_biggemm_f16(int dummy) {
    __shared__ __half Asm[4][64 * ASTR];
    __shared__ __half Bsm[4][32 * BSTR];

    int rb = blockIdx.x, half = blockIdx.y, b = blockIdx.z;
    int row0 = rb * 64;
    const __half* Abh = g_Ah + (size_t)b * Nc * ACOLS + (size_t)half * NEc;
    const __half* Sbh = &g_sh[half][b][0][0];

    int t = threadIdx.x, lane = t & 31, warp = t >> 5;

    const __half* asrc[2]; uint32_t adst[2];
#pragma unroll
    for (int j = 0; j < 2; j++) {
        int flat = j * 128 + t;
        int row = flat >> 2, seg = flat & 3;
        int gr = row0 + row; if (gr > Nc - 1) gr = Nc - 1;
        asrc[j] = Abh + (size_t)gr * ACOLS + seg * 8;
        adst[j] = (uint32_t)(row * ASTR + seg * 8) * 2u;
    }
    const __half* bsrc[2]; uint32_t bdst[2];
#pragma unroll
    for (int j = 0; j < 2; j++) {
        int flat = j * 128 + t;
        int row = flat >> 3, seg = flat & 7;
        bsrc[j] = Sbh + (size_t)row * Dc + seg * 8;
        bdst[j] = (uint32_t)(row * BSTR + seg * 8) * 2u;
    }

    uint32_t a_base[4], b_base[4];
#pragma unroll
    for (int s = 0; s < 4; s++) {
        a_base[s] = (uint32_t)__cvta_generic_to_shared(&Asm[s][0]);
        b_base[s] = (uint32_t)__cvta_generic_to_shared(&Bsm[s][0]);
    }

    uint32_t a_off[2];
#pragma unroll
    for (int kk = 0; kk < 2; kk++) {
        int row = warp * 16 + ((lane >> 3) & 1) * 8 + (lane & 7);
        int col = kk * 16 + (lane >> 4) * 8;
        a_off[kk] = (uint32_t)(row * ASTR + col) * 2u;
    }
    uint32_t b_off[4][2];
#pragma unroll
    for (int g = 0; g < 4; g++)
#pragma unroll
        for (int kk = 0; kk < 2; kk++) {
            int krow = kk * 16 + (lane & 15);
            int ncol = g * 16 + (lane >> 4) * 8;
            b_off[g][kk] = (uint32_t)(krow * BSTR + ncol) * 2u;
        }

    float acc[8][4];
#pragma unroll
    for (int nt = 0; nt < 8; nt++)
#pragma unroll
        for (int c = 0; c < 4; c++) acc[nt][c] = 0.f;

#pragma unroll
    for (int ch = 0; ch < 3; ch++) {
        int kt = ch * KCH;
#pragma unroll
        for (int j = 0; j < 2; j++) {
            cp_async16(a_base[ch] + adst[j], asrc[j] + kt);
            cp_async16(b_base[ch] + bdst[j], bsrc[j] + (size_t)kt * Dc);
        }
        cp_commit();
    }

    for (int i = 0; i < NCHUNK; i++) {
        asm volatile("cp.async.wait_group 2;\n");
        __syncthreads();

        if (i + 3 < NCHUNK) {
            int s = (i + 3) & 3;
            int kt = (i + 3) * KCH;
#pragma unroll
            for (int j = 0; j < 2; j++) {
                cp_async16(a_base[s] + adst[j], asrc[j] + kt);
                cp_async16(b_base[s] + bdst[j], bsrc[j] + (size_t)kt * Dc);
            }
        }
        cp_commit();

        uint32_t ab = a_base[i & 3], bb = b_base[i & 3];
        uint32_t aF[2][4];
        uint32_t bF[2][4][4];
#pragma unroll
        for (int kk = 0; kk < 2; kk++) ldm4(aF[kk], ab + a_off[kk]);
#pragma unroll
        for (int kk = 0; kk < 2; kk++)
#pragma unroll
            for (int g = 0; g < 4; g++) ldm4t(bF[kk][g], bb + b_off[g][kk]);

#pragma unroll
        for (int kk = 0; kk < 2; kk++)
#pragma unroll
            for (int nt = 0; nt < 8; nt++) {
                int g = nt >> 1, sel = nt & 1;
                mma_f16(acc[nt], aF[kk],
                        bF[kk][g][sel * 2], bF[kk][g][sel * 2 + 1]);
            }
    }

    float (*C)[Dc] = g_a[half][b];
    int r_a = row0 + warp * 16 + (lane >> 2);
    int r_b = r_a + 8;
#pragma unroll
    for (int nt = 0; nt < 8; nt++) {
        int col = nt * 8 + (lane & 3) * 2;
        if (r_a < Nc) *(float2*)&C[r_a][col] = make_float2(acc[nt][0], acc[nt][1]);
        if (r_b < Nc) *(float2*)&C[r_b][col] = make_float2(acc[nt][2], acc[nt][3]);
    }
}

// ---------------------------------------------------------------------------
// GRU GEMM 1: P(8000x192) = [a_in | a_out | state] @ WT
// grid (125, 3), block 256.
// ---------------------------------------------------------------------------
__global__ void __launch_bounds__(256) k_gruA(const float* __restrict__ ext_state,
                                              int use_ext) {
    int rb = blockIdx.x, cb = blockIdx.y;
    __shared__ float x_sm[64][64];
    __shared__ float w_sm[64][64];
    int t = threadIdx.x;
    int ty = t >> 5, tx = t & 31;

    float acc[8][2];
#pragma unroll
    for (int i = 0; i < 8; i++) { acc[i][0] = 0.f; acc[i][1] = 0.f; }

    for (int kc = 0; kc < 3; kc++) {
#pragma unroll
        for (int i = 0; i < 4; i++) {
            int idx = i * 256 + t;
            int r = idx >> 4, c4 = idx & 15;
            int gr = rb * 64 + r;
            int b = gr / 1000, n = gr % 1000;
            float4 v;
            if (kc == 0)      v = *(const float4*)&g_a[0][b][n][c4 * 4];
            else if (kc == 1) v = *(const float4*)&g_a[1][b][n][c4 * 4];
            else {
                const float* sp = use_ext ? (ext_state + (size_t)gr * 64)
                                          : &g_state[0][b][n][0];
                v = *(const float4*)&sp[c4 * 4];
            }
            *(float4*)&x_sm[r][c4 * 4] = v;
        }
#pragma unroll
        for (int i = 0; i < 4; i++) {
            int idx = i * 256 + t;
            int k = idx >> 4, ol4 = idx & 15;
            *(float4*)&w_sm[k][ol4 * 4] =
                *(const float4*)&g_WT[kc * 64 + k][cb * 64 + ol4 * 4];
        }
        __syncthreads();

#pragma unroll
        for (int k4 = 0; k4 < 16; k4++) {
            float4 xv[8];
#pragma unroll
            for (int i = 0; i < 8; i++) xv[i] = *(float4*)&x_sm[ty * 8 + i][k4 * 4];
#pragma unroll
            for (int q = 0; q < 4; q++) {
                float2 wv = *(float2*)&w_sm[k4 * 4 + q][tx * 2];
#pragma unroll
                for (int i = 0; i < 8; i++) {
                    float xs = (q == 0) ? xv[i].x : (q == 1) ? xv[i].y
                             : (q == 2) ? xv[i].z : xv[i].w;
                    acc[i][0] += xs * wv.x;
                    acc[i][1] += xs * wv.y;
                }
            }
        }
        __syncthreads();
    }

#pragma unroll
    for (int i = 0; i < 8; i++) {
        int gr = rb * 64 + ty * 8 + i;
        *(float2*)&g_P[gr][cb * 64 + tx * 2] = make_float2(acc[i][0], acc[i][1]);
    }
}

// ---------------------------------------------------------------------------
// GRU GEMM 2 + gate epilogue (rs computed inline from P_r and state):
//   rs = sigm(P_r)*state; H2 = rs @ Wh2T; h = tanh(P_h + H2);
//   z = sigm(P_z); newstate = (1-z)*state + z*h
// grid 125, block 256.
// ---------------------------------------------------------------------------
__global__ void __launch_bounds__(256) k_gruC(const float* __restrict__ ext_state,
                                              int use_ext, int out_idx) {
    int rb = blockIdx.x;
    __shared__ float x_sm[64][64];
    __shared__ float w_sm[64][64];
    int t = threadIdx.x;
    int ty = t >> 5, tx = t & 31;

    // x_sm = rs = sigmoid(P_r) * state
#pragma unroll
    for (int i = 0; i < 4; i++) {
        int idx = i * 256 + t;
        int r = idx >> 4, c4 = idx & 15;
        int gr = rb * 64 + r;
        int b = gr / 1000, n = gr % 1000;
        float4 p = *(const float4*)&g_P[gr][c4 * 4];
        const float* sp = use_ext ? (ext_state + (size_t)gr * 64)
                                  : &g_state[0][b][n][0];
        float4 st = *(const float4*)&sp[c4 * 4];
        float4 o;
        o.x = st.x / (1.f + expf(-p.x));
        o.y = st.y / (1.f + expf(-p.y));
        o.z = st.z / (1.f + expf(-p.z));
        o.w = st.w / (1.f + expf(-p.w));
        *(float4*)&x_sm[r][c4 * 4] = o;
    }
#pragma unroll
    for (int i = 0; i < 4; i++) {
        int idx = i * 256 + t;
        int k = idx >> 4, f4 = idx & 15;
        *(float4*)&w_sm[k][f4 * 4] = *(const float4*)&g_Wh2T[k][f4 * 4];
    }
    __syncthreads();

    float acc[8][2];
#pragma unroll
    for (int i = 0; i < 8; i++) { acc[i][0] = 0.f; acc[i][1] = 0.f; }

#pragma unroll
    for (int k4 = 0; k4 < 16; k4++) {
        float4 xv[8];
#pragma unroll
        for (int i = 0; i < 8; i++) xv[i] = *(float4*)&x_sm[ty * 8 + i][k4 * 4];
#pragma unroll
        for (int q = 0; q < 4; q++) {
            float2 wv = *(float2*)&w_sm[k4 * 4 + q][tx * 2];
#pragma unroll
            for (int i = 0; i < 8; i++) {
                float xs = (q == 0) ? xv[i].x : (q == 1) ? xv[i].y
                         : (q == 2) ? xv[i].z : xv[i].w;
                acc[i][0] += xs * wv.x;
                acc[i][1] += xs * wv.y;
            }
        }
    }

    int f = tx * 2;
#pragma unroll
    for (int i = 0; i < 8; i++) {
        int gr = rb * 64 + ty * 8 + i;
        int b = gr / 1000, n = gr % 1000;
        float2 pz = *(float2*)&g_P[gr][64 + f];
        float2 ph = *(float2*)&g_P[gr][128 + f];
        const float* sp = use_ext ? (ext_state + (size_t)gr * 64)
                                  : &g_state[0][b][n][0];
        float2 st = *(float2*)&sp[f];
        float z0 = 1.f / (1.f + expf(-pz.x));
        float z1 = 1.f / (1.f + expf(-pz.y));
        float h0 = tanhf(ph.x + acc[i][0]);
        float h1 = tanhf(ph.y + acc[i][1]);
        float2 o = make_float2((1.f - z0) * st.x + z0 * h0,
                               (1.f - z1) * st.y + z1 * h1);
        *(float2*)&g_state[out_idx][b][n][f] = o;
    }
}

// ---------------------------------------------------------------------------
// out[b,n] = sum_f tanh( sum_{j<96} [s2|annot][j] * Wo1[f,j] ) * Wo2[f]
// ---------------------------------------------------------------------------
__global__ void k_final(const float* __restrict__ annotation,
                        const float* __restrict__ Wo1,
                        const float* __restrict__ Wo2,
                        float* __restrict__ out) {
    __shared__ float join[4][96];
    __shared__ float terms[4][64];
    int t = threadIdx.x;
    int base = blockIdx.x * 4;

    for (int idx = t; idx < 4 * 96; idx += 256) {
        int lr = idx / 96, j = idx % 96;
        int bn = base + lr;
        int b = bn / Nc, n = bn % Nc;
        join[lr][j] = (j < Dc) ? g_state[1][b][n][j]
                               : annotation[(size_t)bn * ADc + (j - Dc)];
    }
    __syncthreads();

    int f = t & 63, q = t >> 6;
    const float4* w = (const float4*)(Wo1 + (size_t)f * 96);
    float acc = 0.f;
#pragma unroll
    for (int j4 = 0; j4 < 24; j4++) {
        float4 wv = w[j4];
        float4 jv = *(float4*)&join[q][j4 * 4];
        acc += wv.x * jv.x + wv.y * jv.y + wv.z * jv.z + wv.w * jv.w;
    }
    terms[q][f] = tanhf(acc) * Wo2[f];
    __syncthreads();

    if (f == 0) {
        float s = 0.f;
#pragma unroll
        for (int i = 0; i < Dc; i++) s += terms[q][i];
        out[base + q] = s;
    }
}

// ---------------------------------------------------------------------------
extern "C" void kernel_launch(void* const* d_in, const int* in_sizes, int n_in,
                              void* d_out, int out_size) {
    const float* prop_state = (const float*)d_in[0];
    const float* annotation = (const float*)d_in[1];
    const float* A          = (const float*)d_in[2];
    const float* W_in       = (const float*)d_in[3];
    const float* W_out      = (const float*)d_in[4];
    const float* W_r        = (const float*)d_in[5];
    const float* W_z        = (const float*)d_in[6];
    const float* W_h        = (const float*)d_in[7];
    const float* Wo1        = (const float*)d_in[8];
    const float* Wo2        = (const float*)d_in[9];
    float* out = (float*)d_out;

    static int smem_set = 0;
    if (!smem_set) {
        cudaFuncSetAttribute(k_biggemm_f32cvt,
                             cudaFuncAttributeMaxDynamicSharedMemorySize, DSM_CVT);
        smem_set = 1;
    }

    dim3 s_grid(125, 8);
    dim3 gemm_grid(16, 2, Bc);
    dim3 gruA_grid(125, 3);

    k_prepW<<<144, 256>>>(W_r, W_z, W_h);

    // ---- propagate step 1 (state = prop_state): fused conversion GEMM ----
    k_compute_s2<<<s_grid, 256>>>(prop_state, 1, W_in, W_out);
    k_biggemm_f32cvt<<<gemm_grid, 128, DSM_CVT>>>(A);
    k_gruA<<<gruA_grid, 256>>>(prop_state, 1);
    k_gruC<<<125, 256>>>(prop_state, 1, 0);

    // ---- propagate step 2 (state = g_state[0]): pure fp16 GEMM ----
    k_compute_s2<<<s_grid, 256>>>(nullptr, 0, W_in, W_out);
    k_biggemm_f16<<<gemm_grid, 128>>>(0);
    k_gruA<<<gruA_grid, 256>>>(nullptr, 0);
    k_gruC<<<125, 256>>>(nullptr, 0, 1);

    // ---- output head ----
    k_final<<<Bc * Nc / 4, 256>>>(annotation, Wo1, Wo2, out);
}

// round 13
// speedup vs baseline: 1.1034x; 1.1034x over previous
#include <cuda_runtime.h>
#include <cuda_fp16.h>
#include <math.h>
#include <stdint.h>

#define Bc     8
#define Nc     1000
#define Dc     64
#define ADc    32
#define NEc    4000      // E * N
#define ACOLS  8000      // 2 * E * N
#define KCH    32        // K per chunk
#define NCHUNK 125       // 4000 / 32
#define ASTR   40        // fp16 A smem stride (halves)
#define BSTR   72        // B smem stride (halves)

// biggemm 8-stage pipeline geometry
#define A_STG_B (64 * ASTR * 2)            // 5120 B per A stage
#define B_STG_B (32 * BSTR * 2)            // 4608 B per B stage
#define DSM_G   (8 * (A_STG_B + B_STG_B))  // 77824 B

// Scratch (static device globals; no allocation)
__device__ __half g_Ah[(size_t)Bc * Nc * ACOLS];   // fp16 copy of A (128 MB)
__device__ __half g_sh[2][Bc][NEc][Dc];            // S (fp16), k-major rows
__device__ float  g_a[2][Bc][Nc][Dc];              // a_in / a_out
__device__ float  g_state[2][Bc][Nc][Dc];          // s1 / s2
__device__ float  g_WT[192][192];                  // [k][out]: r|z|h (h state-cols zeroed)
__device__ float  g_Wh2T[Dc][Dc];                  // [k][f] = W_h[f][128+k]

// ---------------------------------------------------------------------------
// helpers
// ---------------------------------------------------------------------------
__device__ __forceinline__ void cp_async16(uint32_t dst, const void* src) {
    asm volatile("cp.async.cg.shared.global [%0], [%1], 16;\n" :: "r"(dst), "l"(src));
}
__device__ __forceinline__ void cp_commit() {
    asm volatile("cp.async.commit_group;\n");
}
__device__ __forceinline__ void ldm4(uint32_t* r, uint32_t addr) {
    asm volatile("ldmatrix.sync.aligned.m8n8.x4.shared.b16 {%0,%1,%2,%3}, [%4];"
                 : "=r"(r[0]), "=r"(r[1]), "=r"(r[2]), "=r"(r[3]) : "r"(addr));
}
__device__ __forceinline__ void ldm4t(uint32_t* r, uint32_t addr) {
    asm volatile("ldmatrix.sync.aligned.m8n8.x4.trans.shared.b16 {%0,%1,%2,%3}, [%4];"
                 : "=r"(r[0]), "=r"(r[1]), "=r"(r[2]), "=r"(r[3]) : "r"(addr));
}
__device__ __forceinline__ void mma_f16(float* c, const uint32_t* a,
                                        uint32_t b0, uint32_t b1) {
    asm volatile("mma.sync.aligned.m16n8k16.row.col.f32.f16.f16.f32 "
                 "{%0,%1,%2,%3},{%4,%5,%6,%7},{%8,%9},{%0,%1,%2,%3};"
                 : "+f"(c[0]), "+f"(c[1]), "+f"(c[2]), "+f"(c[3])
                 : "r"(a[0]), "r"(a[1]), "r"(a[2]), "r"(a[3]), "r"(b0), "r"(b1));
}

// ---------------------------------------------------------------------------
// A fp32 -> fp16 (one pass)
// ---------------------------------------------------------------------------
__global__ void __launch_bounds__(256) k_convA(const float* __restrict__ A) {
    size_t idx = (size_t)blockIdx.x * 256 + threadIdx.x;
    float4 v = ((const float4*)A)[idx];
    __half2 h0 = __floats2half2_rn(v.x, v.y);
    __half2 h1 = __floats2half2_rn(v.z, v.w);
    ((uint2*)g_Ah)[idx] = make_uint2(*(uint32_t*)&h0, *(uint32_t*)&h1);
}

// ---------------------------------------------------------------------------
// One-time weight transposes for the GRU GEMMs
// ---------------------------------------------------------------------------
__global__ void __launch_bounds__(256) k_prepW(const float* __restrict__ W_r,
                                               const float* __restrict__ W_z,
                                               const float* __restrict__ W_h) {
    int idx = blockIdx.x * 256 + threadIdx.x;
    if (idx < 192 * 192) {
        int k = idx / 192, out = idx % 192;
        int grp = out >> 6, f = out & 63;
        const float* W = (grp == 0) ? W_r : (grp == 1) ? W_z : W_h;
        float v = W[f * 192 + k];
        if (grp == 2 && k >= 128) v = 0.f;
        g_WT[k][out] = v;
    }
    if (idx < 64 * 64) {
        int k = idx / 64, f = idx % 64;
        g_Wh2T[k][f] = W_h[f * 192 + 128 + k];
    }
}

// ---------------------------------------------------------------------------
// s projection (tiled GEMM) -> fp16 S, k-major rows
// grid (125, 8), block 256.
// ---------------------------------------------------------------------------
__global__ void __launch_bounds__(256) k_compute_s2(
    const float* __restrict__ Xext, int use_ext,
    const float* __restrict__ W_in, const float* __restrict__ W_out) {
    const float* X = use_ext ? Xext : &g_state[0][0][0][0];
    int rb = blockIdx.x, cb = blockIdx.y;
    __shared__ float x_sm[64][64];
    __shared__ float wT[64][64];
    int t = threadIdx.x;

#pragma unroll
    for (int i = 0; i < 4; i++) {
        int idx = i * 256 + t;
        int r = idx >> 4, c4 = idx & 15;
        int gr = rb * 64 + r;
        *(float4*)&x_sm[r][c4 * 4] = *(const float4*)&X[(size_t)gr * 64 + c4 * 4];
    }
    const float* Wsrc = (cb < 4) ? (W_in + (size_t)cb * 64 * 64)
                                 : (W_out + (size_t)(cb - 4) * 64 * 64);
#pragma unroll
    for (int i = 0; i < 4; i++) {
        int idx = i * 256 + t;
        int cl = idx >> 4, k4 = idx & 15;
        float4 v = *(const float4*)&Wsrc[cl * 64 + k4 * 4];
        wT[k4 * 4 + 0][cl] = v.x;
        wT[k4 * 4 + 1][cl] = v.y;
        wT[k4 * 4 + 2][cl] = v.z;
        wT[k4 * 4 + 3][cl] = v.w;
    }
    __syncthreads();

    int ty = t >> 5, tx = t & 31;
    float acc[8][2];
#pragma unroll
    for (int i = 0; i < 8; i++) { acc[i][0] = 0.f; acc[i][1] = 0.f; }

#pragma unroll
    for (int k4 = 0; k4 < 16; k4++) {
        float4 xv[8];
#pragma unroll
        for (int i = 0; i < 8; i++) xv[i] = *(float4*)&x_sm[ty * 8 + i][k4 * 4];
#pragma unroll
        for (int q = 0; q < 4; q++) {
            float2 wv = *(float2*)&wT[k4 * 4 + q][tx * 2];
#pragma unroll
            for (int i = 0; i < 8; i++) {
                float xs = (q == 0) ? xv[i].x : (q == 1) ? xv[i].y
                         : (q == 2) ? xv[i].z : xv[i].w;
                acc[i][0] += xs * wv.x;
                acc[i][1] += xs * wv.y;
            }
        }
    }

    int cbase = cb * 64 + tx * 2;
    int half = cbase >> 8, e = (cbase >> 6) & 3, f = cbase & 63;
#pragma unroll
    for (int i = 0; i < 8; i++) {
        int gr = rb * 64 + ty * 8 + i;
        int b = gr / 1000, n = gr % 1000;
        __half2 hv = __floats2half2_rn(acc[i][0], acc[i][1]);
        *(__half2*)&g_sh[half][b][e * 1000 + n][f] = hv;
    }
}

// ---------------------------------------------------------------------------
// Big adjacency GEMM, fp16 mma + ldmatrix, cp.async 8-stage pipeline.
// grid (16, 2, 8), 128 threads (4 warps; warp tile 16m x 64n). 76 KB dyn smem.
// ---------------------------------------------------------------------------
__global__ void __launch_bounds__(128) k_biggemm_f16(int dummy) {
    extern __shared__ char dsm[];
    __half* Asm = (__half*)dsm;                   // 8 stages x 64*ASTR
    __half* Bsm = (__half*)(dsm + 8 * A_STG_B);   // 8 stages x 32*BSTR

    int rb = blockIdx.x, half = blockIdx.y, b = blockIdx.z;
    int row0 = rb * 64;
    const __half* Abh = g_Ah + (size_t)b * Nc * ACOLS + (size_t)half * NEc;
    const __half* Sbh = &g_sh[half][b][0][0];

    int t = threadIdx.x, lane = t & 31, warp = t >> 5;

    const __half* asrc[2]; uint32_t adst[2];
#pragma unroll
    for (int j = 0; j < 2; j++) {
        int flat = j * 128 + t;
        int row = flat >> 2, seg = flat & 3;           // 64 rows x 4 x 16B
        int gr = row0 + row; if (gr > Nc - 1) gr = Nc - 1;
        asrc[j] = Abh + (size_t)gr * ACOLS + seg * 8;
        adst[j] = (uint32_t)(row * ASTR + seg * 8) * 2u;
    }
    const __half* bsrc[2]; uint32_t bdst[2];
#pragma unroll
    for (int j = 0; j < 2; j++) {
        int flat = j * 128 + t;
        int row = flat >> 3, seg = flat & 7;           // 32 rows x 8 x 16B
        bsrc[j] = Sbh + (size_t)row * Dc + seg * 8;
        bdst[j] = (uint32_t)(row * BSTR + seg * 8) * 2u;
    }

    uint32_t a0 = (uint32_t)__cvta_generic_to_shared(Asm);
    uint32_t b0 = (uint32_t)__cvta_generic_to_shared(Bsm);

    uint32_t a_off[2];
#pragma unroll
    for (int kk = 0; kk < 2; kk++) {
        int row = warp * 16 + ((lane >> 3) & 1) * 8 + (lane & 7);
        int col = kk * 16 + (lane >> 4) * 8;
        a_off[kk] = (uint32_t)(row * ASTR + col) * 2u;
    }
    uint32_t b_off[4][2];
#pragma unroll
    for (int g = 0; g < 4; g++)
#pragma unroll
        for (int kk = 0; kk < 2; kk++) {
            int krow = kk * 16 + (lane & 15);
            int ncol = g * 16 + (lane >> 4) * 8;
            b_off[g][kk] = (uint32_t)(krow * BSTR + ncol) * 2u;
        }

    float acc[8][4];
#pragma unroll
    for (int nt = 0; nt < 8; nt++)
#pragma unroll
        for (int c = 0; c < 4; c++) acc[nt][c] = 0.f;

    // prologue: chunks 0..6
#pragma unroll
    for (int ch = 0; ch < 7; ch++) {
        int kt = ch * KCH;
        uint32_t ab = a0 + (uint32_t)ch * A_STG_B;
        uint32_t bb = b0 + (uint32_t)ch * B_STG_B;
#pragma unroll
        for (int j = 0; j < 2; j++) {
            cp_async16(ab + adst[j], asrc[j] + kt);
            cp_async16(bb + bdst[j], bsrc[j] + (size_t)kt * Dc);
        }
        cp_commit();
    }

    for (int i = 0; i < NCHUNK; i++) {
        asm volatile("cp.async.wait_group 6;\n");
        __syncthreads();

        if (i + 7 < NCHUNK) {
            int s = (i + 7) & 7;
            int kt = (i + 7) * KCH;
            uint32_t ab = a0 + (uint32_t)s * A_STG_B;
            uint32_t bb = b0 + (uint32_t)s * B_STG_B;
#pragma unroll
            for (int j = 0; j < 2; j++) {
                cp_async16(ab + adst[j], asrc[j] + kt);
                cp_async16(bb + bdst[j], bsrc[j] + (size_t)kt * Dc);
            }
        }
        cp_commit();

        uint32_t ab = a0 + (uint32_t)(i & 7) * A_STG_B;
        uint32_t bb = b0 + (uint32_t)(i & 7) * B_STG_B;
        uint32_t aF[2][4];
        uint32_t bF[2][4][4];
#pragma unroll
        for (int kk = 0; kk < 2; kk++) ldm4(aF[kk], ab + a_off[kk]);
#pragma unroll
        for (int kk = 0; kk < 2; kk++)
#pragma unroll
            for (int g = 0; g < 4; g++) ldm4t(bF[kk][g], bb + b_off[g][kk]);

#pragma unroll
        for (int kk = 0; kk < 2; kk++)
#pragma unroll
            for (int nt = 0; nt < 8; nt++) {
                int g = nt >> 1, sel = nt & 1;
                mma_f16(acc[nt], aF[kk],
                        bF[kk][g][sel * 2], bF[kk][g][sel * 2 + 1]);
            }
    }

    float (*C)[Dc] = g_a[half][b];
    int r_a = row0 + warp * 16 + (lane >> 2);
    int r_b = r_a + 8;
#pragma unroll
    for (int nt = 0; nt < 8; nt++) {
        int col = nt * 8 + (lane & 3) * 2;
        if (r_a < Nc) *(float2*)&C[r_a][col] = make_float2(acc[nt][0], acc[nt][1]);
        if (r_b < Nc) *(float2*)&C[r_b][col] = make_float2(acc[nt][2], acc[nt][3]);
    }
}

// ---------------------------------------------------------------------------
// Fully fused GRU: P = [a_in|a_out|state] @ WT; rs = sigm(P_r)*state;
// H2 = rs @ Wh2T; h = tanh(P_h + H2); z = sigm(P_z);
// newstate = (1-z)*state + z*h.
// grid 250 (32-row tiles), block 256 (ty=t>>5 covers rows ty*4+i).
// Inputs loaded into smem ONCE; W tiles streamed from L2.
// ---------------------------------------------------------------------------
__global__ void __launch_bounds__(256) k_gru(const float* __restrict__ ext_state,
                                             int use_ext, int out_idx) {
    __shared__ float x3[3][32][64];    // a_in | a_out | state chunks
    __shared__ float w_sm[64][64];
    int rb = blockIdx.x;               // rows rb*32 .. rb*32+31
    int t = threadIdx.x;
    int ty = t >> 5, tx = t & 31;

    // ---- load inputs once ----
#pragma unroll
    for (int kc = 0; kc < 3; kc++) {
#pragma unroll
        for (int i = 0; i < 2; i++) {
            int idx = i * 256 + t;
            int r = idx >> 4, c4 = idx & 15;
            int gr = rb * 32 + r;
            int b = gr / 1000, n = gr % 1000;
            float4 v;
            if (kc == 0)      v = *(const float4*)&g_a[0][b][n][c4 * 4];
            else if (kc == 1) v = *(const float4*)&g_a[1][b][n][c4 * 4];
            else {
                const float* sp = use_ext ? (ext_state + (size_t)gr * 64)
                                          : &g_state[0][b][n][0];
                v = *(const float4*)&sp[c4 * 4];
            }
            *(float4*)&x3[kc][r][c4 * 4] = v;
        }
    }
    __syncthreads();

    // ---- P GEMM: 3 col-blocks x 3 K-chunks ----
    float acc[3][4][2];
#pragma unroll
    for (int cb = 0; cb < 3; cb++)
#pragma unroll
        for (int i = 0; i < 4; i++) { acc[cb][i][0] = 0.f; acc[cb][i][1] = 0.f; }

    for (int cb = 0; cb < 3; cb++) {
        for (int kc = 0; kc < 3; kc++) {
#pragma unroll
            for (int i = 0; i < 4; i++) {
                int idx = i * 256 + t;
                int k = idx >> 4, o4 = idx & 15;
                *(float4*)&w_sm[k][o4 * 4] =
                    *(const float4*)&g_WT[kc * 64 + k][cb * 64 + o4 * 4];
            }
            __syncthreads();

#pragma unroll
            for (int k4 = 0; k4 < 16; k4++) {
                float4 xv[4];
#pragma unroll
                for (int i = 0; i < 4; i++) xv[i] = *(float4*)&x3[kc][ty * 4 + i][k4 * 4];
#pragma unroll
                for (int q = 0; q < 4; q++) {
                    float2 wv = *(float2*)&w_sm[k4 * 4 + q][tx * 2];
#pragma unroll
                    for (int i = 0; i < 4; i++) {
                        float xs = (q == 0) ? xv[i].x : (q == 1) ? xv[i].y
                                 : (q == 2) ? xv[i].z : xv[i].w;
                        acc[cb][i][0] += xs * wv.x;
                        acc[cb][i][1] += xs * wv.y;
                    }
                }
            }
            __syncthreads();
        }
    }

    // ---- rs = sigm(P_r) * state, written into x3[0] (a_in dead) ----
#pragma unroll
    for (int i = 0; i < 4; i++) {
        int row = ty * 4 + i;
        float2 st = *(float2*)&x3[2][row][tx * 2];
        float2 o;
        o.x = st.x / (1.f + expf(-acc[0][i][0]));
        o.y = st.y / (1.f + expf(-acc[0][i][1]));
        *(float2*)&x3[0][row][tx * 2] = o;
    }
    __syncthreads();

    // ---- H2 GEMM: rs @ Wh2T ----
#pragma unroll
    for (int i = 0; i < 4; i++) {
        int idx = i * 256 + t;
        int k = idx >> 4, f4 = idx & 15;
        *(float4*)&w_sm[k][f4 * 4] = *(const float4*)&g_Wh2T[k][f4 * 4];
    }
    __syncthreads();

    float acc2[4][2];
#pragma unroll
    for (int i = 0; i < 4; i++) { acc2[i][0] = 0.f; acc2[i][1] = 0.f; }

#pragma unroll
    for (int k4 = 0; k4 < 16; k4++) {
        float4 xv[4];
#pragma unroll
        for (int i = 0; i < 4; i++) xv[i] = *(float4*)&x3[0][ty * 4 + i][k4 * 4];
#pragma unroll
        for (int q = 0; q < 4; q++) {
            float2 wv = *(float2*)&w_sm[k4 * 4 + q][tx * 2];
#pragma unroll
            for (int i = 0; i < 4; i++) {
                float xs = (q == 0) ? xv[i].x : (q == 1) ? xv[i].y
                         : (q == 2) ? xv[i].z : xv[i].w;
                acc2[i][0] += xs * wv.x;
                acc2[i][1] += xs * wv.y;
            }
        }
    }

    // ---- gates + blend ----
#pragma unroll
    for (int i = 0; i < 4; i++) {
        int row = ty * 4 + i;
        int gr = rb * 32 + row;
        int b = gr / 1000, n = gr % 1000;
        float2 st = *(float2*)&x3[2][row][tx * 2];
        float z0 = 1.f / (1.f + expf(-acc[1][i][0]));
        float z1 = 1.f / (1.f + expf(-acc[1][i][1]));
        float h0 = tanhf(acc[2][i][0] + acc2[i][0]);
        float h1 = tanhf(acc[2][i][1] + acc2[i][1]);
        float2 o = make_float2((1.f - z0) * st.x + z0 * h0,
                               (1.f - z1) * st.y + z1 * h1);
        *(float2*)&g_state[out_idx][b][n][tx * 2] = o;
    }
}

// ---------------------------------------------------------------------------
// out[b,n] = sum_f tanh( sum_{j<96} [s2|annot][j] * Wo1[f,j] ) * Wo2[f]
// ---------------------------------------------------------------------------
__global__ void k_final(const float* __restrict__ annotation,
                        const float* __restrict__ Wo1,
                        const float* __restrict__ Wo2,
                        float* __restrict__ out) {
    __shared__ float join[4][96];
    __shared__ float terms[4][64];
    int t = threadIdx.x;
    int base = blockIdx.x * 4;

    for (int idx = t; idx < 4 * 96; idx += 256) {
        int lr = idx / 96, j = idx % 96;
        int bn = base + lr;
        int b = bn / Nc, n = bn % Nc;
        join[lr][j] = (j < Dc) ? g_state[1][b][n][j]
                               : annotation[(size_t)bn * ADc + (j - Dc)];
    }
    __syncthreads();

    int f = t & 63, q = t >> 6;
    const float4* w = (const float4*)(Wo1 + (size_t)f * 96);
    float acc = 0.f;
#pragma unroll
    for (int j4 = 0; j4 < 24; j4++) {
        float4 wv = w[j4];
        float4 jv = *(float4*)&join[q][j4 * 4];
        acc += wv.x * jv.x + wv.y * jv.y + wv.z * jv.z + wv.w * jv.w;
    }
    terms[q][f] = tanhf(acc) * Wo2[f];
    __syncthreads();

    if (f == 0) {
        float s = 0.f;
#pragma unroll
        for (int i = 0; i < Dc; i++) s += terms[q][i];
        out[base + q] = s;
    }
}

// ---------------------------------------------------------------------------
extern "C" void kernel_launch(void* const* d_in, const int* in_sizes, int n_in,
                              void* d_out, int out_size) {
    const float* prop_state = (const float*)d_in[0];
    const float* annotation = (const float*)d_in[1];
    const float* A          = (const float*)d_in[2];
    const float* W_in       = (const float*)d_in[3];
    const float* W_out      = (const float*)d_in[4];
    const float* W_r        = (const float*)d_in[5];
    const float* W_z        = (const float*)d_in[6];
    const float* W_h        = (const float*)d_in[7];
    const float* Wo1        = (const float*)d_in[8];
    const float* Wo2        = (const float*)d_in[9];
    float* out = (float*)d_out;

    static int smem_set = 0;
    if (!smem_set) {
        cudaFuncSetAttribute(k_biggemm_f16,
                             cudaFuncAttributeMaxDynamicSharedMemorySize, DSM_G);
        smem_set = 1;
    }

    dim3 s_grid(125, 8);
    dim3 gemm_grid(16, 2, Bc);

    k_convA<<<Bc * Nc * ACOLS / 4 / 256, 256>>>(A);
    k_prepW<<<144, 256>>>(W_r, W_z, W_h);

    // ---- propagate step 1 (state = prop_state) ----
    k_compute_s2<<<s_grid, 256>>>(prop_state, 1, W_in, W_out);
    k_biggemm_f16<<<gemm_grid, 128, DSM_G>>>(0);
    k_gru<<<250, 256>>>(prop_state, 1, 0);

    // ---- propagate step 2 (state = g_state[0]) ----
    k_compute_s2<<<s_grid, 256>>>(nullptr, 0, W_in, W_out);
    k_biggemm_f16<<<gemm_grid, 128, DSM_G>>>(0);
    k_gru<<<250, 256>>>(nullptr, 0, 1);

    // ---- output head ----
    k_final<<<Bc * Nc / 4, 256>>>(annotation, Wo1, Wo2, out);
}

// round 14
// speedup vs baseline: 1.3122x; 1.1893x over previous
#include <cuda_runtime.h>
#include <cuda_fp16.h>
#include <math.h>
#include <stdint.h>

#define Bc     8
#define Nc     1000
#define Dc     64
#define ADc    32
#define NEc    4000      // E * N
#define ACOLS  8000      // 2 * E * N
#define KCH    32        // K per chunk
#define NCHUNK 125       // 4000 / 32
#define ASTR   40        // fp16 A smem stride (halves)
#define BSTR   72        // B smem stride (halves)

// k_gru smem geometry (bytes)
#define XSTR   200       // X stride (halves)
#define WSTR   72        // W stride (halves)
#define RSTR   72        // rs stride (halves)
#define SSTR   68        // state stride (floats)
#define XH_B   (64 * XSTR * 2)            // 25600
#define W_B    (192 * WSTR * 2)           // 27648
#define RS_B   (64 * RSTR * 2)            // 9216
#define ST_B   (64 * SSTR * 4)            // 17408
#define GRU_SMEM (XH_B + W_B + RS_B + ST_B)   // 79872

// Scratch (static device globals; no allocation)
__device__ __half g_Ah[(size_t)Bc * Nc * ACOLS];   // fp16 copy of A (128 MB)
__device__ __half g_sh[2][Bc][NEc][Dc];            // S (fp16), k-major rows
__device__ __half g_ah2[2][Bc][Nc][Dc];            // a_in / a_out (fp16)
__device__ float  g_state[2][Bc][Nc][Dc];          // s1 / s2 (fp32)
__device__ __half g_WTh[192][192];                 // [k][out]: r|z|h fp16 (h k>=128 zeroed)
__device__ __half g_Wh2Th[Dc][Dc];                 // [k][f] = W_h[f][128+k] fp16

// ---------------------------------------------------------------------------
// helpers
// ---------------------------------------------------------------------------
__device__ __forceinline__ void cp_async16(uint32_t dst, const void* src) {
    asm volatile("cp.async.cg.shared.global [%0], [%1], 16;\n" :: "r"(dst), "l"(src));
}
__device__ __forceinline__ void cp_commit() {
    asm volatile("cp.async.commit_group;\n");
}
__device__ __forceinline__ void ldm4(uint32_t* r, uint32_t addr) {
    asm volatile("ldmatrix.sync.aligned.m8n8.x4.shared.b16 {%0,%1,%2,%3}, [%4];"
                 : "=r"(r[0]), "=r"(r[1]), "=r"(r[2]), "=r"(r[3]) : "r"(addr));
}
__device__ __forceinline__ void ldm4t(uint32_t* r, uint32_t addr) {
    asm volatile("ldmatrix.sync.aligned.m8n8.x4.trans.shared.b16 {%0,%1,%2,%3}, [%4];"
                 : "=r"(r[0]), "=r"(r[1]), "=r"(r[2]), "=r"(r[3]) : "r"(addr));
}
__device__ __forceinline__ void mma_f16(float* c, const uint32_t* a,
                                        uint32_t b0, uint32_t b1) {
    asm volatile("mma.sync.aligned.m16n8k16.row.col.f32.f16.f16.f32 "
                 "{%0,%1,%2,%3},{%4,%5,%6,%7},{%8,%9},{%0,%1,%2,%3};"
                 : "+f"(c[0]), "+f"(c[1]), "+f"(c[2]), "+f"(c[3])
                 : "r"(a[0]), "r"(a[1]), "r"(a[2]), "r"(a[3]), "r"(b0), "r"(b1));
}

// ---------------------------------------------------------------------------
// A fp32 -> fp16 (one pass)
// ---------------------------------------------------------------------------
__global__ void __launch_bounds__(256) k_convA(const float* __restrict__ A) {
    size_t idx = (size_t)blockIdx.x * 256 + threadIdx.x;
    float4 v = ((const float4*)A)[idx];
    __half2 h0 = __floats2half2_rn(v.x, v.y);
    __half2 h1 = __floats2half2_rn(v.z, v.w);
    ((uint2*)g_Ah)[idx] = make_uint2(*(uint32_t*)&h0, *(uint32_t*)&h1);
}

// ---------------------------------------------------------------------------
// One-time weight prep (fp16): WTh [k][out] with h-block k>=128 zeroed; Wh2Th.
// ---------------------------------------------------------------------------
__global__ void __launch_bounds__(256) k_prepW(const float* __restrict__ W_r,
                                               const float* __restrict__ W_z,
                                               const float* __restrict__ W_h) {
    int idx = blockIdx.x * 256 + threadIdx.x;
    if (idx < 192 * 192) {
        int k = idx / 192, out = idx % 192;
        int grp = out >> 6, f = out & 63;
        const float* W = (grp == 0) ? W_r : (grp == 1) ? W_z : W_h;
        float v = W[f * 192 + k];
        if (grp == 2 && k >= 128) v = 0.f;
        g_WTh[k][out] = __float2half_rn(v);
    }
    if (idx < 64 * 64) {
        int k = idx / 64, f = idx % 64;
        g_Wh2Th[k][f] = __float2half_rn(W_h[f * 192 + 128 + k]);
    }
}

// ---------------------------------------------------------------------------
// s projection (tiled GEMM) -> fp16 S, k-major rows. grid (125, 8), block 256.
// ---------------------------------------------------------------------------
__global__ void __launch_bounds__(256) k_compute_s2(
    const float* __restrict__ Xext, int use_ext,
    const float* __restrict__ W_in, const float* __restrict__ W_out) {
    const float* X = use_ext ? Xext : &g_state[0][0][0][0];
    int rb = blockIdx.x, cb = blockIdx.y;
    __shared__ float x_sm[64][64];
    __shared__ float wT[64][64];
    int t = threadIdx.x;

#pragma unroll
    for (int i = 0; i < 4; i++) {
        int idx = i * 256 + t;
        int r = idx >> 4, c4 = idx & 15;
        int gr = rb * 64 + r;
        *(float4*)&x_sm[r][c4 * 4] = *(const float4*)&X[(size_t)gr * 64 + c4 * 4];
    }
    const float* Wsrc = (cb < 4) ? (W_in + (size_t)cb * 64 * 64)
                                 : (W_out + (size_t)(cb - 4) * 64 * 64);
#pragma unroll
    for (int i = 0; i < 4; i++) {
        int idx = i * 256 + t;
        int cl = idx >> 4, k4 = idx & 15;
        float4 v = *(const float4*)&Wsrc[cl * 64 + k4 * 4];
        wT[k4 * 4 + 0][cl] = v.x;
        wT[k4 * 4 + 1][cl] = v.y;
        wT[k4 * 4 + 2][cl] = v.z;
        wT[k4 * 4 + 3][cl] = v.w;
    }
    __syncthreads();

    int ty = t >> 5, tx = t & 31;
    float acc[8][2];
#pragma unroll
    for (int i = 0; i < 8; i++) { acc[i][0] = 0.f; acc[i][1] = 0.f; }

#pragma unroll
    for (int k4 = 0; k4 < 16; k4++) {
        float4 xv[8];
#pragma unroll
        for (int i = 0; i < 8; i++) xv[i] = *(float4*)&x_sm[ty * 8 + i][k4 * 4];
#pragma unroll
        for (int q = 0; q < 4; q++) {
            float2 wv = *(float2*)&wT[k4 * 4 + q][tx * 2];
#pragma unroll
            for (int i = 0; i < 8; i++) {
                float xs = (q == 0) ? xv[i].x : (q == 1) ? xv[i].y
                         : (q == 2) ? xv[i].z : xv[i].w;
                acc[i][0] += xs * wv.x;
                acc[i][1] += xs * wv.y;
            }
        }
    }

    int cbase = cb * 64 + tx * 2;
    int half = cbase >> 8, e = (cbase >> 6) & 3, f = cbase & 63;
#pragma unroll
    for (int i = 0; i < 8; i++) {
        int gr = rb * 64 + ty * 8 + i;
        int b = gr / 1000, n = gr % 1000;
        __half2 hv = __floats2half2_rn(acc[i][0], acc[i][1]);
        *(__half2*)&g_sh[half][b][e * 1000 + n][f] = hv;
    }
}

// ---------------------------------------------------------------------------
// Big adjacency GEMM (exact R8 config; epilogue now emits fp16 g_ah2):
// grid (16, 2, 8), 128 threads, 4-stage cp.async, 39 KB static smem.
// ---------------------------------------------------------------------------
__global__ void __launch_bounds__(128) k_biggemm_f16(int dummy) {
    __shared__ __half Asm[4][64 * ASTR];
    __shared__ __half Bsm[4][32 * BSTR];

    int rb = blockIdx.x, half = blockIdx.y, b = blockIdx.z;
    int row0 = rb * 64;
    const __half* Abh = g_Ah + (size_t)b * Nc * ACOLS + (size_t)half * NEc;
    const __half* Sbh = &g_sh[half][b][0][0];

    int t = threadIdx.x, lane = t & 31, warp = t >> 5;

    const __half* asrc[2]; uint32_t adst[2];
#pragma unroll
    for (int j = 0; j < 2; j++) {
        int flat = j * 128 + t;
        int row = flat >> 2, seg = flat & 3;
        int gr = row0 + row; if (gr > Nc - 1) gr = Nc - 1;
        asrc[j] = Abh + (size_t)gr * ACOLS + seg * 8;
        adst[j] = (uint32_t)(row * ASTR + seg * 8) * 2u;
    }
    const __half* bsrc[2]; uint32_t bdst[2];
#pragma unroll
    for (int j = 0; j < 2; j++) {
        int flat = j * 128 + t;
        int row = flat >> 3, seg = flat & 7;
        bsrc[j] = Sbh + (size_t)row * Dc + seg * 8;
        bdst[j] = (uint32_t)(row * BSTR + seg * 8) * 2u;
    }

    uint32_t a_base[4], b_base[4];
#pragma unroll
    for (int s = 0; s < 4; s++) {
        a_base[s] = (uint32_t)__cvta_generic_to_shared(&Asm[s][0]);
        b_base[s] = (uint32_t)__cvta_generic_to_shared(&Bsm[s][0]);
    }

    uint32_t a_off[2];
#pragma unroll
    for (int kk = 0; kk < 2; kk++) {
        int row = warp * 16 + ((lane >> 3) & 1) * 8 + (lane & 7);
        int col = kk * 16 + (lane >> 4) * 8;
        a_off[kk] = (uint32_t)(row * ASTR + col) * 2u;
    }
    uint32_t b_off[4][2];
#pragma unroll
    for (int g = 0; g < 4; g++)
#pragma unroll
        for (int kk = 0; kk < 2; kk++) {
            int krow = kk * 16 + (lane & 15);
            int ncol = g * 16 + (lane >> 4) * 8;
            b_off[g][kk] = (uint32_t)(krow * BSTR + ncol) * 2u;
        }

    float acc[8][4];
#pragma unroll
    for (int nt = 0; nt < 8; nt++)
#pragma unroll
        for (int c = 0; c < 4; c++) acc[nt][c] = 0.f;

#pragma unroll
    for (int ch = 0; ch < 3; ch++) {
        int kt = ch * KCH;
#pragma unroll
        for (int j = 0; j < 2; j++) {
            cp_async16(a_base[ch] + adst[j], asrc[j] + kt);
            cp_async16(b_base[ch] + bdst[j], bsrc[j] + (size_t)kt * Dc);
        }
        cp_commit();
    }

    for (int i = 0; i < NCHUNK; i++) {
        asm volatile("cp.async.wait_group 2;\n");
        __syncthreads();

        if (i + 3 < NCHUNK) {
            int s = (i + 3) & 3;
            int kt = (i + 3) * KCH;
#pragma unroll
            for (int j = 0; j < 2; j++) {
                cp_async16(a_base[s] + adst[j], asrc[j] + kt);
                cp_async16(b_base[s] + bdst[j], bsrc[j] + (size_t)kt * Dc);
            }
        }
        cp_commit();

        uint32_t ab = a_base[i & 3], bb = b_base[i & 3];
        uint32_t aF[2][4];
        uint32_t bF[2][4][4];
#pragma unroll
        for (int kk = 0; kk < 2; kk++) ldm4(aF[kk], ab + a_off[kk]);
#pragma unroll
        for (int kk = 0; kk < 2; kk++)
#pragma unroll
            for (int g = 0; g < 4; g++) ldm4t(bF[kk][g], bb + b_off[g][kk]);

#pragma unroll
        for (int kk = 0; kk < 2; kk++)
#pragma unroll
            for (int nt = 0; nt < 8; nt++) {
                int g = nt >> 1, sel = nt & 1;
                mma_f16(acc[nt], aF[kk],
                        bF[kk][g][sel * 2], bF[kk][g][sel * 2 + 1]);
            }
    }

    __half (*C)[Dc] = g_ah2[half][b];
    int r_a = row0 + warp * 16 + (lane >> 2);
    int r_b = r_a + 8;
#pragma unroll
    for (int nt = 0; nt < 8; nt++) {
        int col = nt * 8 + (lane & 3) * 2;
        if (r_a < Nc) *(__half2*)&C[r_a][col] = __floats2half2_rn(acc[nt][0], acc[nt][1]);
        if (r_b < Nc) *(__half2*)&C[r_b][col] = __floats2half2_rn(acc[nt][2], acc[nt][3]);
    }
}

// ---------------------------------------------------------------------------
// Fused tensor-core GRU. grid 125 (64-row tiles), 128 threads (4 warps,
// warp tile 16m x 64n). P = X @ WTh (X=[a_in|a_out|state] fp16, K=192);
// rs = sigm(P_r)*state -> fp16 smem; H2 = rs @ Wh2Th; gates fp32.
// ---------------------------------------------------------------------------
__global__ void __launch_bounds__(128) k_gru(const float* __restrict__ ext_state,
                                             int use_ext, int out_idx) {
    extern __shared__ char gsm[];
    __half* Xh  = (__half*)gsm;                    // [64][200]
    __half* Wsm = (__half*)(gsm + XH_B);           // [192][72] (reused for Wh2 [64][72])
    __half* RSs = (__half*)(gsm + XH_B + W_B);     // [64][72]
    float*  STs = (float*)(gsm + XH_B + W_B + RS_B); // [64][68]

    int rb = blockIdx.x;
    int row0 = rb * 64;
    int t = threadIdx.x, lane = t & 31, warp = t >> 5;

    uint32_t xh_u  = (uint32_t)__cvta_generic_to_shared(Xh);
    uint32_t wsm_u = (uint32_t)__cvta_generic_to_shared(Wsm);
    uint32_t rs_u  = (uint32_t)__cvta_generic_to_shared(RSs);

    // ---- load a_in/a_out into Xh cols [0,128) via cp.async ----
#pragma unroll
    for (int j = 0; j < 8; j++) {
        int flat = j * 128 + t;
        int row = flat >> 4, seg = flat & 15;      // 64 rows x 16 segs of 8 halves
        int gr = row0 + row;
        int b = gr / 1000, n = gr % 1000;
        const __half* p = (seg < 8) ? &g_ah2[0][b][n][seg * 8]
                                    : &g_ah2[1][b][n][(seg - 8) * 8];
        cp_async16(xh_u + (uint32_t)(row * XSTR + seg * 8) * 2u, p);
    }
    // ---- W(cb=0) ----
#pragma unroll
    for (int j = 0; j < 12; j++) {
        int flat = j * 128 + t;
        int k = flat >> 3, seg = flat & 7;         // 192 rows x 8 segs
        cp_async16(wsm_u + (uint32_t)(k * WSTR + seg * 8) * 2u, &g_WTh[k][seg * 8]);
    }
    cp_commit();
    // ---- state fp32 -> STs + fp16 -> Xh cols [128,192) ----
#pragma unroll
    for (int j = 0; j < 8; j++) {
        int flat = j * 128 + t;
        int row = flat >> 4, c4 = flat & 15;       // 64 rows x 16 float4
        int gr = row0 + row;
        int b = gr / 1000, n = gr % 1000;
        const float* sp = use_ext ? (ext_state + (size_t)gr * 64)
                                  : &g_state[0][b][n][0];
        float4 v = *(const float4*)&sp[c4 * 4];
        *(float4*)&STs[row * SSTR + c4 * 4] = v;
        __half2 h0 = __floats2half2_rn(v.x, v.y);
        __half2 h1 = __floats2half2_rn(v.z, v.w);
        *(uint2*)&Xh[row * XSTR + 128 + c4 * 4] = make_uint2(*(uint32_t*)&h0, *(uint32_t*)&h1);
    }

    // fragment bases
    int a_row = warp * 16 + ((lane >> 3) & 1) * 8 + (lane & 7);
    int acol8 = (lane >> 4) * 8;
    uint32_t base_a  = xh_u + (uint32_t)(a_row * XSTR + acol8) * 2u;
    uint32_t base_rs = rs_u + (uint32_t)(a_row * RSTR + acol8) * 2u;
    int b_k = lane & 15, bcol = (lane >> 4) * 8;

    float acc[3][8][4];
#pragma unroll
    for (int cb = 0; cb < 3; cb++)
#pragma unroll
        for (int nt = 0; nt < 8; nt++)
#pragma unroll
            for (int c = 0; c < 4; c++) acc[cb][nt][c] = 0.f;

    // ---- P GEMM: 3 col-blocks, each K=192 in 6 chunks ----
    for (int cb = 0; cb < 3; cb++) {
        asm volatile("cp.async.wait_group 0;\n");
        __syncthreads();

#pragma unroll
        for (int kc = 0; kc < 6; kc++) {
#pragma unroll
            for (int kk = 0; kk < 2; kk++) {
                int kb = kc * 32 + kk * 16;
                uint32_t aF[4];
                ldm4(aF, base_a + (uint32_t)kb * 2u);
                uint32_t bF[4][4];
#pragma unroll
                for (int g = 0; g < 4; g++)
                    ldm4t(bF[g], wsm_u + (uint32_t)((kb + b_k) * WSTR + g * 16 + bcol) * 2u);
#pragma unroll
                for (int nt = 0; nt < 8; nt++) {
                    int g = nt >> 1, sel = nt & 1;
                    mma_f16(acc[cb][nt], aF, bF[g][sel * 2], bF[g][sel * 2 + 1]);
                }
            }
        }
        __syncthreads();   // done reading Wsm

        if (cb < 2) {      // next P weight block
#pragma unroll
            for (int j = 0; j < 12; j++) {
                int flat = j * 128 + t;
                int k = flat >> 3, seg = flat & 7;
                cp_async16(wsm_u + (uint32_t)(k * WSTR + seg * 8) * 2u,
                           &g_WTh[k][(cb + 1) * 64 + seg * 8]);
            }
        } else {           // Wh2 into Wsm head
#pragma unroll
            for (int j = 0; j < 4; j++) {
                int flat = j * 128 + t;
                int k = flat >> 3, seg = flat & 7;
                cp_async16(wsm_u + (uint32_t)(k * WSTR + seg * 8) * 2u,
                           &g_Wh2Th[k][seg * 8]);
            }
        }
        cp_commit();
    }

    // ---- rs = sigm(P_r) * state -> RSs (fp16) ----
    int lr_a = warp * 16 + (lane >> 2);
    int lr_b = lr_a + 8;
#pragma unroll
    for (int nt = 0; nt < 8; nt++) {
        int c = nt * 8 + (lane & 3) * 2;
        float2 sa = *(float2*)&STs[lr_a * SSTR + c];
        float2 sb = *(float2*)&STs[lr_b * SSTR + c];
        float ra0 = sa.x / (1.f + expf(-acc[0][nt][0]));
        float ra1 = sa.y / (1.f + expf(-acc[0][nt][1]));
        float rb0 = sb.x / (1.f + expf(-acc[0][nt][2]));
        float rb1 = sb.y / (1.f + expf(-acc[0][nt][3]));
        *(__half2*)&RSs[lr_a * RSTR + c] = __floats2half2_rn(ra0, ra1);
        *(__half2*)&RSs[lr_b * RSTR + c] = __floats2half2_rn(rb0, rb1);
    }
    asm volatile("cp.async.wait_group 0;\n");
    __syncthreads();   // Wh2 ready, RSs visible

    // ---- H2 GEMM (reuse acc[0]) ----
#pragma unroll
    for (int nt = 0; nt < 8; nt++)
#pragma unroll
        for (int c = 0; c < 4; c++) acc[0][nt][c] = 0.f;

#pragma unroll
    for (int kc = 0; kc < 2; kc++) {
#pragma unroll
        for (int kk = 0; kk < 2; kk++) {
            int kb = kc * 32 + kk * 16;
            uint32_t aF[4];
            ldm4(aF, base_rs + (uint32_t)kb * 2u);
            uint32_t bF[4][4];
#pragma unroll
            for (int g = 0; g < 4; g++)
                ldm4t(bF[g], wsm_u + (uint32_t)((kb + b_k) * WSTR + g * 16 + bcol) * 2u);
#pragma unroll
            for (int nt = 0; nt < 8; nt++) {
                int g = nt >> 1, sel = nt & 1;
                mma_f16(acc[0][nt], aF, bF[g][sel * 2], bF[g][sel * 2 + 1]);
            }
        }
    }

    // ---- gates + blend -> g_state[out_idx] (fp32) ----
#pragma unroll
    for (int nt = 0; nt < 8; nt++) {
        int c = nt * 8 + (lane & 3) * 2;
        float2 sa = *(float2*)&STs[lr_a * SSTR + c];
        float2 sb = *(float2*)&STs[lr_b * SSTR + c];
        float za0 = 1.f / (1.f + expf(-acc[1][nt][0]));
        float za1 = 1.f / (1.f + expf(-acc[1][nt][1]));
        float zb0 = 1.f / (1.f + expf(-acc[1][nt][2]));
        float zb1 = 1.f / (1.f + expf(-acc[1][nt][3]));
        float ha0 = tanhf(acc[2][nt][0] + acc[0][nt][0]);
        float ha1 = tanhf(acc[2][nt][1] + acc[0][nt][1]);
        float hb0 = tanhf(acc[2][nt][2] + acc[0][nt][2]);
        float hb1 = tanhf(acc[2][nt][3] + acc[0][nt][3]);
        int gra = row0 + lr_a, grb = row0 + lr_b;
        int ba = gra / 1000, na = gra % 1000;
        int bb2 = grb / 1000, nb = grb % 1000;
        *(float2*)&g_state[out_idx][ba][na][c] =
            make_float2((1.f - za0) * sa.x + za0 * ha0,
                        (1.f - za1) * sa.y + za1 * ha1);
        *(float2*)&g_state[out_idx][bb2][nb][c] =
            make_float2((1.f - zb0) * sb.x + zb0 * hb0,
                        (1.f - zb1) * sb.y + zb1 * hb1);
    }
}

// ---------------------------------------------------------------------------
// out[b,n] = sum_f tanh( sum_{j<96} [s2|annot][j] * Wo1[f,j] ) * Wo2[f]
// ---------------------------------------------------------------------------
__global__ void k_final(const float* __restrict__ annotation,
                        const float* __restrict__ Wo1,
                        const float* __restrict__ Wo2,
                        float* __restrict__ out) {
    __shared__ float join[4][96];
    __shared__ float terms[4][64];
    int t = threadIdx.x;
    int base = blockIdx.x * 4;

    for (int idx = t; idx < 4 * 96; idx += 256) {
        int lr = idx / 96, j = idx % 96;
        int bn = base + lr;
        int b = bn / Nc, n = bn % Nc;
        join[lr][j] = (j < Dc) ? g_state[1][b][n][j]
                               : annotation[(size_t)bn * ADc + (j - Dc)];
    }
    __syncthreads();

    int f = t & 63, q = t >> 6;
    const float4* w = (const float4*)(Wo1 + (size_t)f * 96);
    float acc = 0.f;
#pragma unroll
    for (int j4 = 0; j4 < 24; j4++) {
        float4 wv = w[j4];
        float4 jv = *(float4*)&join[q][j4 * 4];
        acc += wv.x * jv.x + wv.y * jv.y + wv.z * jv.z + wv.w * jv.w;
    }
    terms[q][f] = tanhf(acc) * Wo2[f];
    __syncthreads();

    if (f == 0) {
        float s = 0.f;
#pragma unroll
        for (int i = 0; i < Dc; i++) s += terms[q][i];
        out[base + q] = s;
    }
}

// ---------------------------------------------------------------------------
extern "C" void kernel_launch(void* const* d_in, const int* in_sizes, int n_in,
                              void* d_out, int out_size) {
    const float* prop_state = (const float*)d_in[0];
    const float* annotation = (const float*)d_in[1];
    const float* A          = (const float*)d_in[2];
    const float* W_in       = (const float*)d_in[3];
    const float* W_out      = (const float*)d_in[4];
    const float* W_r        = (const float*)d_in[5];
    const float* W_z        = (const float*)d_in[6];
    const float* W_h        = (const float*)d_in[7];
    const float* Wo1        = (const float*)d_in[8];
    const float* Wo2        = (const float*)d_in[9];
    float* out = (float*)d_out;

    static int smem_set = 0;
    if (!smem_set) {
        cudaFuncSetAttribute(k_gru,
                             cudaFuncAttributeMaxDynamicSharedMemorySize, GRU_SMEM);
        smem_set = 1;
    }

    dim3 s_grid(125, 8);
    dim3 gemm_grid(16, 2, Bc);

    k_convA<<<Bc * Nc * ACOLS / 4 / 256, 256>>>(A);
    k_prepW<<<144, 256>>>(W_r, W_z, W_h);

    // ---- propagate step 1 (state = prop_state) ----
    k_compute_s2<<<s_grid, 256>>>(prop_state, 1, W_in, W_out);
    k_biggemm_f16<<<gemm_grid, 128>>>(0);
    k_gru<<<125, 128, GRU_SMEM>>>(prop_state, 1, 0);

    // ---- propagate step 2 (state = g_state[0]) ----
    k_compute_s2<<<s_grid, 256>>>(nullptr, 0, W_in, W_out);
    k_biggemm_f16<<<gemm_grid, 128>>>(0);
    k_gru<<<125, 128, GRU_SMEM>>>(nullptr, 0, 1);

    // ---- output head ----
    k_final<<<Bc * Nc / 4, 256>>>(annotation, Wo1, Wo2, out);
}

// round 15
// speedup vs baseline: 1.3325x; 1.0155x over previous
#include <cuda_runtime.h>
#include <cuda_fp16.h>
#include <math.h>
#include <stdint.h>

#define Bc     8
#define Nc     1000
#define Dc     64
#define ADc    32
#define NEc    4000      // E * N
#define ACOLS  8000      // 2 * E * N
#define KCH    32        // K per chunk
#define NCHUNK 125       // 4000 / 32
#define ASTR   40        // fp16 A smem stride (halves)
#define BSTR   72        // B smem stride (halves)
#define CHW    32000     // halves per chunk slab in tiled A' (1000*32)

// k_gru smem geometry (bytes)
#define XSTR   200       // X stride (halves)
#define WSTR   72        // W stride (halves)
#define RSTR   72        // rs stride (halves)
#define SSTR   68        // state stride (floats)
#define XH_B   (64 * XSTR * 2)            // 25600
#define W_B    (192 * WSTR * 2)           // 27648
#define RS_B   (64 * RSTR * 2)            // 9216
#define ST_B   (64 * SSTR * 4)            // 17408
#define GRU_SMEM (XH_B + W_B + RS_B + ST_B)   // 79872

// Scratch (static device globals; no allocation)
// g_Ah: chunk-tiled fp16 A': [b][half][ch][n][32]  (128 MB)
__device__ __half g_Ah[(size_t)Bc * 2 * NCHUNK * CHW];
__device__ __half g_sh[2][Bc][NEc][Dc];            // S (fp16), k-major rows
__device__ __half g_ah2[2][Bc][Nc][Dc];            // a_in / a_out (fp16)
__device__ float  g_state[2][Bc][Nc][Dc];          // s1 / s2 (fp32)
__device__ __half g_WTh[192][192];                 // [k][out]: r|z|h fp16 (h k>=128 zeroed)
__device__ __half g_Wh2Th[Dc][Dc];                 // [k][f] = W_h[f][128+k] fp16

// ---------------------------------------------------------------------------
// helpers
// ---------------------------------------------------------------------------
__device__ __forceinline__ void cp_async16(uint32_t dst, const void* src) {
    asm volatile("cp.async.cg.shared.global [%0], [%1], 16;\n" :: "r"(dst), "l"(src));
}
__device__ __forceinline__ void cp_commit() {
    asm volatile("cp.async.commit_group;\n");
}
__device__ __forceinline__ void ldm4(uint32_t* r, uint32_t addr) {
    asm volatile("ldmatrix.sync.aligned.m8n8.x4.shared.b16 {%0,%1,%2,%3}, [%4];"
                 : "=r"(r[0]), "=r"(r[1]), "=r"(r[2]), "=r"(r[3]) : "r"(addr));
}
__device__ __forceinline__ void ldm4t(uint32_t* r, uint32_t addr) {
    asm volatile("ldmatrix.sync.aligned.m8n8.x4.trans.shared.b16 {%0,%1,%2,%3}, [%4];"
                 : "=r"(r[0]), "=r"(r[1]), "=r"(r[2]), "=r"(r[3]) : "r"(addr));
}
__device__ __forceinline__ void mma_f16(float* c, const uint32_t* a,
                                        uint32_t b0, uint32_t b1) {
    asm volatile("mma.sync.aligned.m16n8k16.row.col.f32.f16.f16.f32 "
                 "{%0,%1,%2,%3},{%4,%5,%6,%7},{%8,%9},{%0,%1,%2,%3};"
                 : "+f"(c[0]), "+f"(c[1]), "+f"(c[2]), "+f"(c[3])
                 : "r"(a[0]), "r"(a[1]), "r"(a[2]), "r"(a[3]), "r"(b0), "r"(b1));
}

// ---------------------------------------------------------------------------
// A fp32 -> fp16, chunk-tiled: A'[b][half][ch][n][32].
// Reads fully coalesced; writes in 64B sector-complete segments.
// ---------------------------------------------------------------------------
__global__ void __launch_bounds__(256) k_convA(const float* __restrict__ A) {
    size_t idx = (size_t)blockIdx.x * 256 + threadIdx.x;   // float4 index
    float4 v = ((const float4*)A)[idx];
    __half2 h0 = __floats2half2_rn(v.x, v.y);
    __half2 h1 = __floats2half2_rn(v.z, v.w);
    uint2 pk = make_uint2(*(uint32_t*)&h0, *(uint32_t*)&h1);

    size_t bn = idx / 2000;
    int c4 = (int)(idx % 2000);
    int b = (int)(bn / 1000), n = (int)(bn % 1000);
    int c = c4 * 4;
    int half = (c >= NEc) ? 1 : 0;
    int cc = c - half * NEc;
    int ch = cc >> 5, off = cc & 31;
    size_t dsth = (((size_t)b * 2 + half) * NCHUNK + ch) * CHW + (size_t)n * 32 + off;
    *(uint2*)&g_Ah[dsth] = pk;
}

// ---------------------------------------------------------------------------
// One-time weight prep (fp16)
// ---------------------------------------------------------------------------
__global__ void __launch_bounds__(256) k_prepW(const float* __restrict__ W_r,
                                               const float* __restrict__ W_z,
                                               const float* __restrict__ W_h) {
    int idx = blockIdx.x * 256 + threadIdx.x;
    if (idx < 192 * 192) {
        int k = idx / 192, out = idx % 192;
        int grp = out >> 6, f = out & 63;
        const float* W = (grp == 0) ? W_r : (grp == 1) ? W_z : W_h;
        float v = W[f * 192 + k];
        if (grp == 2 && k >= 128) v = 0.f;
        g_WTh[k][out] = __float2half_rn(v);
    }
    if (idx < 64 * 64) {
        int k = idx / 64, f = idx % 64;
        g_Wh2Th[k][f] = __float2half_rn(W_h[f * 192 + 128 + k]);
    }
}

// ---------------------------------------------------------------------------
// s projection (tiled GEMM) -> fp16 S, k-major rows. grid (125, 8), block 256.
// ---------------------------------------------------------------------------
__global__ void __launch_bounds__(256) k_compute_s2(
    const float* __restrict__ Xext, int use_ext,
    const float* __restrict__ W_in, const float* __restrict__ W_out) {
    const float* X = use_ext ? Xext : &g_state[0][0][0][0];
    int rb = blockIdx.x, cb = blockIdx.y;
    __shared__ float x_sm[64][64];
    __shared__ float wT[64][64];
    int t = threadIdx.x;

#pragma unroll
    for (int i = 0; i < 4; i++) {
        int idx = i * 256 + t;
        int r = idx >> 4, c4 = idx & 15;
        int gr = rb * 64 + r;
        *(float4*)&x_sm[r][c4 * 4] = *(const float4*)&X[(size_t)gr * 64 + c4 * 4];
    }
    const float* Wsrc = (cb < 4) ? (W_in + (size_t)cb * 64 * 64)
                                 : (W_out + (size_t)(cb - 4) * 64 * 64);
#pragma unroll
    for (int i = 0; i < 4; i++) {
        int idx = i * 256 + t;
        int cl = idx >> 4, k4 = idx & 15;
        float4 v = *(const float4*)&Wsrc[cl * 64 + k4 * 4];
        wT[k4 * 4 + 0][cl] = v.x;
        wT[k4 * 4 + 1][cl] = v.y;
        wT[k4 * 4 + 2][cl] = v.z;
        wT[k4 * 4 + 3][cl] = v.w;
    }
    __syncthreads();

    int ty = t >> 5, tx = t & 31;
    float acc[8][2];
#pragma unroll
    for (int i = 0; i < 8; i++) { acc[i][0] = 0.f; acc[i][1] = 0.f; }

#pragma unroll
    for (int k4 = 0; k4 < 16; k4++) {
        float4 xv[8];
#pragma unroll
        for (int i = 0; i < 8; i++) xv[i] = *(float4*)&x_sm[ty * 8 + i][k4 * 4];
#pragma unroll
        for (int q = 0; q < 4; q++) {
            float2 wv = *(float2*)&wT[k4 * 4 + q][tx * 2];
#pragma unroll
            for (int i = 0; i < 8; i++) {
                float xs = (q == 0) ? xv[i].x : (q == 1) ? xv[i].y
                         : (q == 2) ? xv[i].z : xv[i].w;
                acc[i][0] += xs * wv.x;
                acc[i][1] += xs * wv.y;
            }
        }
    }

    int cbase = cb * 64 + tx * 2;
    int half = cbase >> 8, e = (cbase >> 6) & 3, f = cbase & 63;
#pragma unroll
    for (int i = 0; i < 8; i++) {
        int gr = rb * 64 + ty * 8 + i;
        int b = gr / 1000, n = gr % 1000;
        __half2 hv = __floats2half2_rn(acc[i][0], acc[i][1]);
        *(__half2*)&g_sh[half][b][e * 1000 + n][f] = hv;
    }
}

// ---------------------------------------------------------------------------
// Big adjacency GEMM (R8 config, chunk-tiled A' reads — contiguous 4KB/chunk):
// grid (16, 2, 8), 128 threads, 4-stage cp.async, 39 KB static smem.
// ---------------------------------------------------------------------------
__global__ void __launch_bounds__(128) k_biggemm_f16(int dummy) {
    __shared__ __half Asm[4][64 * ASTR];
    __shared__ __half Bsm[4][32 * BSTR];

    int rb = blockIdx.x, half = blockIdx.y, b = blockIdx.z;
    int row0 = rb * 64;
    const __half* Abh = g_Ah + ((size_t)b * 2 + half) * NCHUNK * CHW;
    const __half* Sbh = &g_sh[half][b][0][0];

    int t = threadIdx.x, lane = t & 31, warp = t >> 5;

    // A cp.async: 64 rows x 4 segs of 16B (8 halves) within a chunk slab
    const __half* asrc[2]; uint32_t adst[2];
#pragma unroll
    for (int j = 0; j < 2; j++) {
        int flat = j * 128 + t;
        int row = flat >> 2, seg = flat & 3;
        int gr = row0 + row; if (gr > Nc - 1) gr = Nc - 1;
        asrc[j] = Abh + (size_t)gr * 32 + seg * 8;
        adst[j] = (uint32_t)(row * ASTR + seg * 8) * 2u;
    }
    const __half* bsrc[2]; uint32_t bdst[2];
#pragma unroll
    for (int j = 0; j < 2; j++) {
        int flat = j * 128 + t;
        int row = flat >> 3, seg = flat & 7;
        bsrc[j] = Sbh + (size_t)row * Dc + seg * 8;
        bdst[j] = (uint32_t)(row * BSTR + seg * 8) * 2u;
    }

    uint32_t a_base[4], b_base[4];
#pragma unroll
    for (int s = 0; s < 4; s++) {
        a_base[s] = (uint32_t)__cvta_generic_to_shared(&Asm[s][0]);
        b_base[s] = (uint32_t)__cvta_generic_to_shared(&Bsm[s][0]);
    }

    uint32_t a_off[2];
#pragma unroll
    for (int kk = 0; kk < 2; kk++) {
        int row = warp * 16 + ((lane >> 3) & 1) * 8 + (lane & 7);
        int col = kk * 16 + (lane >> 4) * 8;
        a_off[kk] = (uint32_t)(row * ASTR + col) * 2u;
    }
    uint32_t b_off[4][2];
#pragma unroll
    for (int g = 0; g < 4; g++)
#pragma unroll
        for (int kk = 0; kk < 2; kk++) {
            int krow = kk * 16 + (lane & 15);
            int ncol = g * 16 + (lane >> 4) * 8;
            b_off[g][kk] = (uint32_t)(krow * BSTR + ncol) * 2u;
        }

    float acc[8][4];
#pragma unroll
    for (int nt = 0; nt < 8; nt++)
#pragma unroll
        for (int c = 0; c < 4; c++) acc[nt][c] = 0.f;

#pragma unroll
    for (int ch = 0; ch < 3; ch++) {
#pragma unroll
        for (int j = 0; j < 2; j++) {
            cp_async16(a_base[ch] + adst[j], asrc[j] + (size_t)ch * CHW);
            cp_async16(b_base[ch] + bdst[j], bsrc[j] + (size_t)ch * KCH * Dc);
        }
        cp_commit();
    }

    for (int i = 0; i < NCHUNK; i++) {
        asm volatile("cp.async.wait_group 2;\n");
        __syncthreads();

        if (i + 3 < NCHUNK) {
            int s = (i + 3) & 3;
#pragma unroll
            for (int j = 0; j < 2; j++) {
                cp_async16(a_base[s] + adst[j], asrc[j] + (size_t)(i + 3) * CHW);
                cp_async16(b_base[s] + bdst[j], bsrc[j] + (size_t)(i + 3) * KCH * Dc);
            }
        }
        cp_commit();

        uint32_t ab = a_base[i & 3], bb = b_base[i & 3];
        uint32_t aF[2][4];
        uint32_t bF[2][4][4];
#pragma unroll
        for (int kk = 0; kk < 2; kk++) ldm4(aF[kk], ab + a_off[kk]);
#pragma unroll
        for (int kk = 0; kk < 2; kk++)
#pragma unroll
            for (int g = 0; g < 4; g++) ldm4t(bF[kk][g], bb + b_off[g][kk]);

#pragma unroll
        for (int kk = 0; kk < 2; kk++)
#pragma unroll
            for (int nt = 0; nt < 8; nt++) {
                int g = nt >> 1, sel = nt & 1;
                mma_f16(acc[nt], aF[kk],
                        bF[kk][g][sel * 2], bF[kk][g][sel * 2 + 1]);
            }
    }

    __half (*C)[Dc] = g_ah2[half][b];
    int r_a = row0 + warp * 16 + (lane >> 2);
    int r_b = r_a + 8;
#pragma unroll
    for (int nt = 0; nt < 8; nt++) {
        int col = nt * 8 + (lane & 3) * 2;
        if (r_a < Nc) *(__half2*)&C[r_a][col] = __floats2half2_rn(acc[nt][0], acc[nt][1]);
        if (r_b < Nc) *(__half2*)&C[r_b][col] = __floats2half2_rn(acc[nt][2], acc[nt][3]);
    }
}

// ---------------------------------------------------------------------------
// Fused tensor-core GRU (unchanged from R14 winner).
// ---------------------------------------------------------------------------
__global__ void __launch_bounds__(128) k_gru(const float* __restrict__ ext_state,
                                             int use_ext, int out_idx) {
    extern __shared__ char gsm[];
    __half* Xh  = (__half*)gsm;                    // [64][200]
    __half* Wsm = (__half*)(gsm + XH_B);           // [192][72]
    __half* RSs = (__half*)(gsm + XH_B + W_B);     // [64][72]
    float*  STs = (float*)(gsm + XH_B + W_B + RS_B); // [64][68]

    int rb = blockIdx.x;
    int row0 = rb * 64;
    int t = threadIdx.x, lane = t & 31, warp = t >> 5;

    uint32_t xh_u  = (uint32_t)__cvta_generic_to_shared(Xh);
    uint32_t wsm_u = (uint32_t)__cvta_generic_to_shared(Wsm);
    uint32_t rs_u  = (uint32_t)__cvta_generic_to_shared(RSs);

#pragma unroll
    for (int j = 0; j < 8; j++) {
        int flat = j * 128 + t;
        int row = flat >> 4, seg = flat & 15;
        int gr = row0 + row;
        int b = gr / 1000, n = gr % 1000;
        const __half* p = (seg < 8) ? &g_ah2[0][b][n][seg * 8]
                                    : &g_ah2[1][b][n][(seg - 8) * 8];
        cp_async16(xh_u + (uint32_t)(row * XSTR + seg * 8) * 2u, p);
    }
#pragma unroll
    for (int j = 0; j < 12; j++) {
        int flat = j * 128 + t;
        int k = flat >> 3, seg = flat & 7;
        cp_async16(wsm_u + (uint32_t)(k * WSTR + seg * 8) * 2u, &g_WTh[k][seg * 8]);
    }
    cp_commit();
#pragma unroll
    for (int j = 0; j < 8; j++) {
        int flat = j * 128 + t;
        int row = flat >> 4, c4 = flat & 15;
        int gr = row0 + row;
        int b = gr / 1000, n = gr % 1000;
        const float* sp = use_ext ? (ext_state + (size_t)gr * 64)
                                  : &g_state[0][b][n][0];
        float4 v = *(const float4*)&sp[c4 * 4];
        *(float4*)&STs[row * SSTR + c4 * 4] = v;
        __half2 h0 = __floats2half2_rn(v.x, v.y);
        __half2 h1 = __floats2half2_rn(v.z, v.w);
        *(uint2*)&Xh[row * XSTR + 128 + c4 * 4] = make_uint2(*(uint32_t*)&h0, *(uint32_t*)&h1);
    }

    int a_row = warp * 16 + ((lane >> 3) & 1) * 8 + (lane & 7);
    int acol8 = (lane >> 4) * 8;
    uint32_t base_a  = xh_u + (uint32_t)(a_row * XSTR + acol8) * 2u;
    uint32_t base_rs = rs_u + (uint32_t)(a_row * RSTR + acol8) * 2u;
    int b_k = lane & 15, bcol = (lane >> 4) * 8;

    float acc[3][8][4];
#pragma unroll
    for (int cb = 0; cb < 3; cb++)
#pragma unroll
        for (int nt = 0; nt < 8; nt++)
#pragma unroll
            for (int c = 0; c < 4; c++) acc[cb][nt][c] = 0.f;

    for (int cb = 0; cb < 3; cb++) {
        asm volatile("cp.async.wait_group 0;\n");
        __syncthreads();

#pragma unroll
        for (int kc = 0; kc < 6; kc++) {
#pragma unroll
            for (int kk = 0; kk < 2; kk++) {
                int kb = kc * 32 + kk * 16;
                uint32_t aF[4];
                ldm4(aF, base_a + (uint32_t)kb * 2u);
                uint32_t bF[4][4];
#pragma unroll
                for (int g = 0; g < 4; g++)
                    ldm4t(bF[g], wsm_u + (uint32_t)((kb + b_k) * WSTR + g * 16 + bcol) * 2u);
#pragma unroll
                for (int nt = 0; nt < 8; nt++) {
                    int g = nt >> 1, sel = nt & 1;
                    mma_f16(acc[cb][nt], aF, bF[g][sel * 2], bF[g][sel * 2 + 1]);
                }
            }
        }
        __syncthreads();

        if (cb < 2) {
#pragma unroll
            for (int j = 0; j < 12; j++) {
                int flat = j * 128 + t;
                int k = flat >> 3, seg = flat & 7;
                cp_async16(wsm_u + (uint32_t)(k * WSTR + seg * 8) * 2u,
                           &g_WTh[k][(cb + 1) * 64 + seg * 8]);
            }
        } else {
#pragma unroll
            for (int j = 0; j < 4; j++) {
                int flat = j * 128 + t;
                int k = flat >> 3, seg = flat & 7;
                cp_async16(wsm_u + (uint32_t)(k * WSTR + seg * 8) * 2u,
                           &g_Wh2Th[k][seg * 8]);
            }
        }
        cp_commit();
    }

    int lr_a = warp * 16 + (lane >> 2);
    int lr_b = lr_a + 8;
#pragma unroll
    for (int nt = 0; nt < 8; nt++) {
        int c = nt * 8 + (lane & 3) * 2;
        float2 sa = *(float2*)&STs[lr_a * SSTR + c];
        float2 sb = *(float2*)&STs[lr_b * SSTR + c];
        float ra0 = sa.x / (1.f + expf(-acc[0][nt][0]));
        float ra1 = sa.y / (1.f + expf(-acc[0][nt][1]));
        float rb0 = sb.x / (1.f + expf(-acc[0][nt][2]));
        float rb1 = sb.y / (1.f + expf(-acc[0][nt][3]));
        *(__half2*)&RSs[lr_a * RSTR + c] = __floats2half2_rn(ra0, ra1);
        *(__half2*)&RSs[lr_b * RSTR + c] = __floats2half2_rn(rb0, rb1);
    }
    asm volatile("cp.async.wait_group 0;\n");
    __syncthreads();

#pragma unroll
    for (int nt = 0; nt < 8; nt++)
#pragma unroll
        for (int c = 0; c < 4; c++) acc[0][nt][c] = 0.f;

#pragma unroll
    for (int kc = 0; kc < 2; kc++) {
#pragma unroll
        for (int kk = 0; kk < 2; kk++) {
            int kb = kc * 32 + kk * 16;
            uint32_t aF[4];
            ldm4(aF, base_rs + (uint32_t)kb * 2u);
            uint32_t bF[4][4];
#pragma unroll
            for (int g = 0; g < 4; g++)
                ldm4t(bF[g], wsm_u + (uint32_t)((kb + b_k) * WSTR + g * 16 + bcol) * 2u);
#pragma unroll
            for (int nt = 0; nt < 8; nt++) {
                int g = nt >> 1, sel = nt & 1;
                mma_f16(acc[0][nt], aF, bF[g][sel * 2], bF[g][sel * 2 + 1]);
            }
        }
    }

#pragma unroll
    for (int nt = 0; nt < 8; nt++) {
        int c = nt * 8 + (lane & 3) * 2;
        float2 sa = *(float2*)&STs[lr_a * SSTR + c];
        float2 sb = *(float2*)&STs[lr_b * SSTR + c];
        float za0 = 1.f / (1.f + expf(-acc[1][nt][0]));
        float za1 = 1.f / (1.f + expf(-acc[1][nt][1]));
        float zb0 = 1.f / (1.f + expf(-acc[1][nt][2]));
        float zb1 = 1.f / (1.f + expf(-acc[1][nt][3]));
        float ha0 = tanhf(acc[2][nt][0] + acc[0][nt][0]);
        float ha1 = tanhf(acc[2][nt][1] + acc[0][nt][1]);
        float hb0 = tanhf(acc[2][nt][2] + acc[0][nt][2]);
        float hb1 = tanhf(acc[2][nt][3] + acc[0][nt][3]);
        int gra = row0 + lr_a, grb = row0 + lr_b;
        int ba = gra / 1000, na = gra % 1000;
        int bb2 = grb / 1000, nb = grb % 1000;
        *(float2*)&g_state[out_idx][ba][na][c] =
            make_float2((1.f - za0) * sa.x + za0 * ha0,
                        (1.f - za1) * sa.y + za1 * ha1);
        *(float2*)&g_state[out_idx][bb2][nb][c] =
            make_float2((1.f - zb0) * sb.x + zb0 * hb0,
                        (1.f - zb1) * sb.y + zb1 * hb1);
    }
}

// ---------------------------------------------------------------------------
// out[b,n] = sum_f tanh( sum_{j<96} [s2|annot][j] * Wo1[f,j] ) * Wo2[f]
// ---------------------------------------------------------------------------
__global__ void k_final(const float* __restrict__ annotation,
                        const float* __restrict__ Wo1,
                        const float* __restrict__ Wo2,
                        float* __restrict__ out) {
    __shared__ float join[4][96];
    __shared__ float terms[4][64];
    int t = threadIdx.x;
    int base = blockIdx.x * 4;

    for (int idx = t; idx < 4 * 96; idx += 256) {
        int lr = idx / 96, j = idx % 96;
        int bn = base + lr;
        int b = bn / Nc, n = bn % Nc;
        join[lr][j] = (j < Dc) ? g_state[1][b][n][j]
                               : annotation[(size_t)bn * ADc + (j - Dc)];
    }
    __syncthreads();

    int f = t & 63, q = t >> 6;
    const float4* w = (const float4*)(Wo1 + (size_t)f * 96);
    float acc = 0.f;
#pragma unroll
    for (int j4 = 0; j4 < 24; j4++) {
        float4 wv = w[j4];
        float4 jv = *(float4*)&join[q][j4 * 4];
        acc += wv.x * jv.x + wv.y * jv.y + wv.z * jv.z + wv.w * jv.w;
    }
    terms[q][f] = tanhf(acc) * Wo2[f];
    __syncthreads();

    if (f == 0) {
        float s = 0.f;
#pragma unroll
        for (int i = 0; i < Dc; i++) s += terms[q][i];
        out[base + q] = s;
    }
}

// ---------------------------------------------------------------------------
extern "C" void kernel_launch(void* const* d_in, const int* in_sizes, int n_in,
                              void* d_out, int out_size) {
    const float* prop_state = (const float*)d_in[0];
    const float* annotation = (const float*)d_in[1];
    const float* A          = (const float*)d_in[2];
    const float* W_in       = (const float*)d_in[3];
    const float* W_out      = (const float*)d_in[4];
    const float* W_r        = (const float*)d_in[5];
    const float* W_z        = (const float*)d_in[6];
    const float* W_h        = (const float*)d_in[7];
    const float* Wo1        = (const float*)d_in[8];
    const float* Wo2        = (const float*)d_in[9];
    float* out = (float*)d_out;

    static int smem_set = 0;
    if (!smem_set) {
        cudaFuncSetAttribute(k_gru,
                             cudaFuncAttributeMaxDynamicSharedMemorySize, GRU_SMEM);
        smem_set = 1;
    }

    dim3 s_grid(125, 8);
    dim3 gemm_grid(16, 2, Bc);

    k_convA<<<Bc * Nc * ACOLS / 4 / 256, 256>>>(A);
    k_prepW<<<144, 256>>>(W_r, W_z, W_h);

    // ---- propagate step 1 (state = prop_state) ----
    k_compute_s2<<<s_grid, 256>>>(prop_state, 1, W_in, W_out);
    k_biggemm_f16<<<gemm_grid, 128>>>(0);
    k_gru<<<125, 128, GRU_SMEM>>>(prop_state, 1, 0);

    // ---- propagate step 2 (state = g_state[0]) ----
    k_compute_s2<<<s_grid, 256>>>(nullptr, 0, W_in, W_out);
    k_biggemm_f16<<<gemm_grid, 128>>>(0);
    k_gru<<<125, 128, GRU_SMEM>>>(nullptr, 0, 1);

    // ---- output head ----
    k_final<<<Bc * Nc / 4, 256>>>(annotation, Wo1, Wo2, out);
}